// round 3
// baseline (speedup 1.0000x reference)
#include <cuda_runtime.h>
#include <math.h>

#define HIDDEN 128
#define NF 128
#define NG 50
#define EB 8
#define RB 8
#define MAXN 40000
#define LN2f 0.69314718055994530942f

typedef unsigned long long u64;

// ---------- packed f32x2 helpers (Blackwell FFMA2 path) ----------
__device__ __forceinline__ u64 pack2(float lo, float hi) {
    u64 r; asm("mov.b64 %0,{%1,%2};" : "=l"(r) : "f"(lo), "f"(hi)); return r;
}
__device__ __forceinline__ u64 dup2(float a) {
    u64 r; asm("mov.b64 %0,{%1,%1};" : "=l"(r) : "f"(a)); return r;
}
__device__ __forceinline__ void unpack2(u64 v, float& lo, float& hi) {
    asm("mov.b64 {%0,%1},%2;" : "=f"(lo), "=f"(hi) : "l"(v));
}
__device__ __forceinline__ void fma2(u64& d, u64 a, u64 b) {
    asm("fma.rn.f32x2 %0,%1,%2,%0;" : "+l"(d) : "l"(a), "l"(b));
}
// vector fp32 atomic reduction (PTX ISA 8.1+, sm_90+)
__device__ __forceinline__ void red_add_v4(float* p, float a, float b, float c, float d) {
    asm volatile("red.global.add.v4.f32 [%0], {%1,%2,%3,%4};"
                 :: "l"(p), "f"(a), "f"(b), "f"(c), "f"(d) : "memory");
}

__device__ __forceinline__ float sspf(float x) {
    // shifted softplus via MUFU: log(1+e^x)-ln2 = max(x,0)+log(0.5*(1+e^-|x|))
    return fmaxf(x, 0.f) + __logf(0.5f * (1.0f + __expf(-fabsf(x))));
}

// ---------- scratch (no allocations allowed) ----------
__device__ float g_h[(size_t)MAXN * NF];
__device__ float g_agg[(size_t)MAXN * NF];
__device__ float g_u[(size_t)MAXN * HIDDEN];

// =================================================================
// Row GEMM, RB rows per warp: Y[n,:] = act( X[n,:] @ W^T + b )
// W row-major [128][128]; lane owns f = 4l..4l+3
// =================================================================
#define ROW_SMEM ((128 * 128 + 128) * 4)

__global__ __launch_bounds__(256)
void row_gemm_kernel(const float* __restrict__ X, const float* __restrict__ W,
                     const float* __restrict__ B, float* __restrict__ Y,
                     int N, int doSsp) {
    extern __shared__ float sm[];
    float* sWT = sm;            // [j][f] = W[f][j]
    float* sB  = sm + 128 * 128;

    int tid = threadIdx.x;
    for (int i = tid; i < 128 * 128; i += blockDim.x) {
        int f = i >> 7, j = i & 127;
        sWT[j * 128 + f] = W[i];
    }
    if (tid < 128) sB[tid] = B ? B[tid] : 0.f;
    __syncthreads();

    int lane = tid & 31, warp = tid >> 5;
    int gw = blockIdx.x * (blockDim.x >> 5) + warp;
    int tw = gridDim.x * (blockDim.x >> 5);
    float4 bv = ((const float4*)sB)[lane];
    u64 blo = pack2(bv.x, bv.y), bhi = pack2(bv.z, bv.w);

    int ngroups = (N + RB - 1) / RB;
    for (int g = gw; g < ngroups; g += tw) {
        int n0 = g * RB;
        float4 xv[RB];
        u64 acc0[RB], acc1[RB];
        #pragma unroll
        for (int r = 0; r < RB; r++) {
            int n = n0 + r;
            xv[r] = (n < N) ? *(const float4*)(X + (size_t)n * 128 + 4 * lane)
                            : make_float4(0.f, 0.f, 0.f, 0.f);
            acc0[r] = blo; acc1[r] = bhi;
        }
        #pragma unroll 2
        for (int s = 0; s < 32; s++) {
            const float* wp = sWT + (s * 4) * 128;
            ulonglong2 r0 = ((const ulonglong2*)(wp      ))[lane];
            ulonglong2 r1 = ((const ulonglong2*)(wp + 128))[lane];
            ulonglong2 r2 = ((const ulonglong2*)(wp + 256))[lane];
            ulonglong2 r3 = ((const ulonglong2*)(wp + 384))[lane];
            #pragma unroll
            for (int r = 0; r < RB; r++) {
                float x0 = __shfl_sync(0xffffffffu, xv[r].x, s);
                float x1 = __shfl_sync(0xffffffffu, xv[r].y, s);
                float x2 = __shfl_sync(0xffffffffu, xv[r].z, s);
                float x3 = __shfl_sync(0xffffffffu, xv[r].w, s);
                u64 a;
                a = dup2(x0); fma2(acc0[r], a, r0.x); fma2(acc1[r], a, r0.y);
                a = dup2(x1); fma2(acc0[r], a, r1.x); fma2(acc1[r], a, r1.y);
                a = dup2(x2); fma2(acc0[r], a, r2.x); fma2(acc1[r], a, r2.y);
                a = dup2(x3); fma2(acc0[r], a, r3.x); fma2(acc1[r], a, r3.y);
            }
        }
        #pragma unroll
        for (int r = 0; r < RB; r++) {
            int n = n0 + r;
            if (n >= N) break;
            float o0, o1, o2, o3;
            unpack2(acc0[r], o0, o1); unpack2(acc1[r], o2, o3);
            if (doSsp) { o0 = sspf(o0); o1 = sspf(o1); o2 = sspf(o2); o3 = sspf(o3); }
            *(float4*)(Y + (size_t)n * 128 + 4 * lane) = make_float4(o0, o1, o2, o3);
        }
    }
}

// =================================================================
// Fused edge kernel, EB=8 edges per warp, 128-thread blocks:
//   t = ssp(attr @ w1^T + b1); Wf = (t @ w2^T + b2) * C(edge_w)
//   msg = h[src] * Wf ; atomic agg[dst] += msg
// =================================================================
#define NWARP 4
#define EDGE_SMEM ((NG * NF + NF * NF + NF + NF + NWARP * EB * NF) * 4)

__global__ __launch_bounds__(128, 2)
void edge_kernel(const float* __restrict__ h, const int* __restrict__ ei,
                 const float* __restrict__ ew, const float* __restrict__ attr,
                 const float* __restrict__ w1, const float* __restrict__ b1,
                 const float* __restrict__ w2, const float* __restrict__ b2,
                 float* __restrict__ agg, int E) {
    extern __shared__ float sm[];
    float* sW1 = sm;                       // [k][f], 50*128
    float* sW2 = sW1 + NG * NF;            // [j][f], 128*128
    float* sB1 = sW2 + NF * NF;            // 128
    float* sB2 = sB1 + NF;                 // 128
    float* sT  = sB2 + NF;                 // [warp][EB][128]

    int tid = threadIdx.x;
    for (int i = tid; i < NG * NF; i += 128) {
        int f = i / NG, k = i - f * NG;
        sW1[k * NF + f] = w1[i];
    }
    for (int i = tid; i < NF * NF; i += 128) {
        int f = i >> 7, j = i & 127;
        sW2[j * NF + f] = w2[i];
    }
    if (tid < NF) { sB1[tid] = b1[tid]; sB2[tid] = b2[tid]; }
    __syncthreads();

    int lane = tid & 31, warp = tid >> 5;
    float4 b1v = ((const float4*)sB1)[lane];
    float4 b2v = ((const float4*)sB2)[lane];
    u64 b1lo = pack2(b1v.x, b1v.y), b1hi = pack2(b1v.z, b1v.w);
    u64 b2lo = pack2(b2v.x, b2v.y), b2hi = pack2(b2v.z, b2v.w);
    float* myT = sT + (warp * EB) * NF;

    int ngroups = (E + EB - 1) / EB;
    int gw = blockIdx.x * NWARP + warp;
    int tw = gridDim.x * NWARP;

    for (int g = gw; g < ngroups; g += tw) {
        int ebase = g * EB;
        float a0[EB], a1[EB], cv[EB];
        int srcv[EB], dstv[EB];
        #pragma unroll
        for (int e = 0; e < EB; e++) {
            int idx = ebase + e;
            bool valid = idx < E;
            int ii = valid ? idx : (E - 1);
            a0[e] = (lane < NG)      ? attr[(size_t)ii * NG + lane]      : 0.f;
            a1[e] = (lane + 32 < NG) ? attr[(size_t)ii * NG + lane + 32] : 0.f;
            srcv[e] = ei[ii];
            dstv[e] = ei[E + ii];
            float w = ew[ii];
            cv[e] = valid ? 0.5f * (cospif(w * 0.1f) + 1.0f) : 0.f;
        }

        // ---- stage 1: t = attr @ w1^T + b1 ----
        u64 T0[EB], T1[EB];
        #pragma unroll
        for (int e = 0; e < EB; e++) { T0[e] = b1lo; T1[e] = b1hi; }
        #pragma unroll 2
        for (int k = 0; k < NG; k++) {
            ulonglong2 wv = ((const ulonglong2*)(sW1 + k * NF))[lane];
            #pragma unroll
            for (int e = 0; e < EB; e++) {
                float av = (k < 32) ? a0[e] : a1[e];
                float a = __shfl_sync(0xffffffffu, av, k & 31);
                u64 aa = dup2(a);
                fma2(T0[e], aa, wv.x);
                fma2(T1[e], aa, wv.y);
            }
        }
        // ssp + stage into smem for stage-2 broadcast
        __syncwarp();
        #pragma unroll
        for (int e = 0; e < EB; e++) {
            float t0, t1, t2, t3;
            unpack2(T0[e], t0, t1); unpack2(T1[e], t2, t3);
            t0 = sspf(t0); t1 = sspf(t1); t2 = sspf(t2); t3 = sspf(t3);
            *(float4*)(myT + e * NF + 4 * lane) = make_float4(t0, t1, t2, t3);
        }
        __syncwarp();

        // ---- stage 2: Wf = t @ w2^T + b2 ----
        u64 U0[EB], U1[EB];
        #pragma unroll
        for (int e = 0; e < EB; e++) { U0[e] = b2lo; U1[e] = b2hi; }
        #pragma unroll 2
        for (int s = 0; s < 32; s++) {
            const float* wp = sW2 + (s * 4) * NF;
            ulonglong2 r0 = ((const ulonglong2*)(wp      ))[lane];
            ulonglong2 r1 = ((const ulonglong2*)(wp + 128))[lane];
            ulonglong2 r2 = ((const ulonglong2*)(wp + 256))[lane];
            ulonglong2 r3 = ((const ulonglong2*)(wp + 384))[lane];
            #pragma unroll
            for (int e = 0; e < EB; e++) {
                float4 tv = *(const float4*)(myT + e * NF + 4 * s);  // LDS broadcast
                u64 a;
                a = dup2(tv.x); fma2(U0[e], a, r0.x); fma2(U1[e], a, r0.y);
                a = dup2(tv.y); fma2(U0[e], a, r1.x); fma2(U1[e], a, r1.y);
                a = dup2(tv.z); fma2(U0[e], a, r2.x); fma2(U1[e], a, r2.y);
                a = dup2(tv.w); fma2(U0[e], a, r3.x); fma2(U1[e], a, r3.y);
            }
        }

        // ---- epilogue: envelope * gather * scatter-add ----
        #pragma unroll
        for (int e = 0; e < EB; e++) {
            float W0, W1, W2, W3;
            unpack2(U0[e], W0, W1); unpack2(U1[e], W2, W3);
            float c = cv[e];
            float4 hv = *(const float4*)(h + (size_t)srcv[e] * NF + 4 * lane);
            float m0 = hv.x * W0 * c;
            float m1 = hv.y * W1 * c;
            float m2 = hv.z * W2 * c;
            float m3 = hv.w * W3 * c;
            red_add_v4(agg + (size_t)dstv[e] * NF + 4 * lane, m0, m1, m2, m3);
        }
        __syncwarp();
    }
}

// =================================================================
extern "C" void kernel_launch(void* const* d_in, const int* in_sizes, int n_in,
                              void* d_out, int out_size) {
    const float* x    = (const float*)d_in[0];
    const int*   ei   = (const int*)  d_in[1];
    const float* ew   = (const float*)d_in[2];
    const float* attr = (const float*)d_in[3];
    const float* w1   = (const float*)d_in[4];
    const float* b1   = (const float*)d_in[5];
    const float* w2   = (const float*)d_in[6];
    const float* b2   = (const float*)d_in[7];
    const float* l1w  = (const float*)d_in[8];
    const float* l2w  = (const float*)d_in[9];
    const float* l2b  = (const float*)d_in[10];
    const float* lw   = (const float*)d_in[11];
    const float* lb   = (const float*)d_in[12];
    float* out = (float*)d_out;

    int N = in_sizes[0] / HIDDEN;
    int E = in_sizes[2];

    void *ph = nullptr, *pagg = nullptr, *pu = nullptr;
    cudaGetSymbolAddress(&ph,   g_h);
    cudaGetSymbolAddress(&pagg, g_agg);
    cudaGetSymbolAddress(&pu,   g_u);

    cudaFuncSetAttribute(row_gemm_kernel, cudaFuncAttributeMaxDynamicSharedMemorySize, ROW_SMEM);
    cudaFuncSetAttribute(edge_kernel,     cudaFuncAttributeMaxDynamicSharedMemorySize, EDGE_SMEM);

    // agg = 0
    cudaMemsetAsync(pagg, 0, (size_t)N * NF * sizeof(float));
    // h = x @ lin1_w^T
    row_gemm_kernel<<<625, 256, ROW_SMEM>>>(x, l1w, nullptr, (float*)ph, N, 0);
    // fused edge filter MLP + CFConv message + scatter
    edge_kernel<<<592, 128, EDGE_SMEM>>>((const float*)ph, ei, ew, attr,
                                         w1, b1, w2, b2, (float*)pagg, E);
    // u = ssp(agg @ lin2_w^T + lin2_b)
    row_gemm_kernel<<<625, 256, ROW_SMEM>>>((const float*)pagg, l2w, l2b, (float*)pu, N, 1);
    // out = u @ lin_w^T + lin_b
    row_gemm_kernel<<<625, 256, ROW_SMEM>>>((const float*)pu, lw, lb, out, N, 0);
}

// round 8
// speedup vs baseline: 1.3622x; 1.3622x over previous
#include <cuda_runtime.h>
#include <cuda_bf16.h>
#include <math.h>
#include <cstdint>

#define HIDDEN 128
#define NF 128
#define NG 50
#define RB 8
#define MAXN 40000

typedef unsigned long long u64;

// ---------- packed f32x2 helpers ----------
__device__ __forceinline__ u64 pack2(float lo, float hi) {
    u64 r; asm("mov.b64 %0,{%1,%2};" : "=l"(r) : "f"(lo), "f"(hi)); return r;
}
__device__ __forceinline__ u64 dup2(float a) {
    u64 r; asm("mov.b64 %0,{%1,%1};" : "=l"(r) : "f"(a)); return r;
}
__device__ __forceinline__ void unpack2(u64 v, float& lo, float& hi) {
    asm("mov.b64 {%0,%1},%2;" : "=f"(lo), "=f"(hi) : "l"(v));
}
__device__ __forceinline__ void fma2(u64& d, u64 a, u64 b) {
    asm("fma.rn.f32x2 %0,%1,%2,%0;" : "+l"(d) : "l"(a), "l"(b));
}
__device__ __forceinline__ void red_add_v2(float* p, float a, float b) {
    asm volatile("red.global.add.v2.f32 [%0], {%1,%2};" :: "l"(p), "f"(a), "f"(b) : "memory");
}
__device__ __forceinline__ float sspf(float x) {
    return fmaxf(x, 0.f) + __logf(0.5f * (1.0f + __expf(-fabsf(x))));
}
__device__ __forceinline__ void bf16_split(float v, float& hi, float& lo) {
    __nv_bfloat16 h = __float2bfloat16(v);
    hi = __bfloat162float(h);
    lo = v - hi;
}
__device__ __forceinline__ uint32_t pack_bf16x2(float v0, float v1) {
    __nv_bfloat162 p = __floats2bfloat162_rn(v0, v1);  // v0 -> low half
    return *(uint32_t*)&p;
}

// mma.sync m16n8k16 bf16 (baseline PTX — works on compute_103 family target)
__device__ __forceinline__ void mma_bf16(float* c, uint32_t a0, uint32_t a1,
                                         uint32_t a2, uint32_t a3,
                                         uint32_t b0, uint32_t b1) {
    asm volatile(
        "mma.sync.aligned.m16n8k16.row.col.f32.bf16.bf16.f32 "
        "{%0,%1,%2,%3}, {%4,%5,%6,%7}, {%8,%9}, {%0,%1,%2,%3};"
        : "+f"(c[0]), "+f"(c[1]), "+f"(c[2]), "+f"(c[3])
        : "r"(a0), "r"(a1), "r"(a2), "r"(a3), "r"(b0), "r"(b1));
}

// ---------- scratch ----------
__device__ float g_h[(size_t)MAXN * NF];
__device__ float g_agg[(size_t)MAXN * NF];
__device__ float g_u[(size_t)MAXN * HIDDEN];
// weight fragment blob: W1HI[4096] W1LO[4096] W2HI[8192] W2LO[8192] uint32 words = 96KB
__device__ uint4 g_wblob[6144];

// ================= prep: build mma B-fragment tables =================
// B frag for D = A @ W^T: n = nt*8 + lane/4 ; k(reg) = kc*16 + (lane%4)*2 + reg*8, pair (k,k+1)
__global__ void prep_weights_kernel(const float* __restrict__ w1,
                                    const float* __restrict__ w2) {
    uint32_t* blob = (uint32_t*)g_wblob;
    int tid = blockIdx.x * blockDim.x + threadIdx.x;
    int stride = gridDim.x * blockDim.x;
    // W1: 16 ntiles x 4 kchunks x 2 regs x 32 lanes = 4096 words
    for (int i = tid; i < 4096; i += stride) {
        int lane = i & 31, reg = (i >> 5) & 1, kc = (i >> 6) & 3, nt = i >> 8;
        int n = nt * 8 + (lane >> 2);
        int k0 = kc * 16 + (lane & 3) * 2 + reg * 8;
        float v0 = (k0 < NG)     ? w1[n * NG + k0]     : 0.f;
        float v1 = (k0 + 1 < NG) ? w1[n * NG + k0 + 1] : 0.f;
        float h0, l0, h1, l1;
        bf16_split(v0, h0, l0); bf16_split(v1, h1, l1);
        blob[i]        = pack_bf16x2(h0, h1);
        blob[4096 + i] = pack_bf16x2(l0, l1);
    }
    // W2: 16 x 8 x 2 x 32 = 8192 words
    for (int i = tid; i < 8192; i += stride) {
        int lane = i & 31, reg = (i >> 5) & 1, kc = (i >> 6) & 7, nt = i >> 9;
        int n = nt * 8 + (lane >> 2);
        int k0 = kc * 16 + (lane & 3) * 2 + reg * 8;
        float v0 = w2[n * 128 + k0];
        float v1 = w2[n * 128 + k0 + 1];
        float h0, l0, h1, l1;
        bf16_split(v0, h0, l0); bf16_split(v1, h1, l1);
        blob[8192 + i]  = pack_bf16x2(h0, h1);
        blob[16384 + i] = pack_bf16x2(l0, l1);
    }
}

// ================= smem layout (uint32 word offsets) =================
#define SW_W1HI   0
#define SW_W1LO   4096
#define SW_W2HI   8192
#define SW_W2LO   16384
#define SW_B1     24576
#define SW_B2     24704
#define SW_CV     24832
#define SW_SRC    24960
#define SW_DST    25088
#define SW_AHI    25216          /* attr hi packed, 128 rows x 33 words */
#define SW_ALO    29440
#define SW_THI    33664          /* T hi packed, 128 rows x 65 words */
#define SW_TLO    41984
#define SW_TOTAL  50304
#define EDGE_SMEM (SW_TOTAL * 4) /* 201216 B */

// ================= fused mma.sync edge kernel =================
// CTA = 128 edges, 256 threads (8 warps), warp w owns rows [16w,16w+16)
__global__ __launch_bounds__(256, 1)
void edge_mma_kernel(const float* __restrict__ h, const int* __restrict__ ei,
                     const float* __restrict__ ew, const float* __restrict__ attr,
                     const float* __restrict__ b1, const float* __restrict__ b2,
                     float* __restrict__ agg, int E) {
    extern __shared__ uint32_t sm[];
    float* smf = (float*)sm;
    int tid = threadIdx.x;
    int warp = tid >> 5, lane = tid & 31;
    int qr = lane >> 2, qc = lane & 3;
    int base = blockIdx.x * 128;

    // ---- load: weight frag blob, biases, edge meta, attr hi/lo packed ----
    {
        uint4* dst = (uint4*)sm;
        const uint4* src = g_wblob;
        #pragma unroll 4
        for (int i = tid; i < 6144; i += 256) dst[i] = src[i];
    }
    if (tid < 128) {
        smf[SW_B1 + tid] = b1[tid];
        smf[SW_B2 + tid] = b2[tid];
        int e = base + tid;
        bool valid = e < E;
        int ie = valid ? e : 0;
        ((int*)sm)[SW_SRC + tid] = ei[ie];
        ((int*)sm)[SW_DST + tid] = ei[E + ie];
        float w = ew[ie];
        smf[SW_CV + tid] = valid ? 0.5f * (cospif(w * 0.1f) + 1.0f) : 0.f;
    }
    for (int i = tid; i < 128 * 32; i += 256) {
        int r = i >> 5, j = i & 31;
        int e = base + r;
        int k0 = 2 * j;
        bool v = e < E;
        float v0 = (v && k0 < NG)     ? attr[(size_t)e * NG + k0]     : 0.f;
        float v1 = (v && k0 + 1 < NG) ? attr[(size_t)e * NG + k0 + 1] : 0.f;
        float h0, l0, h1, l1;
        bf16_split(v0, h0, l0); bf16_split(v1, h1, l1);
        sm[SW_AHI + r * 33 + j] = pack_bf16x2(h0, h1);
        sm[SW_ALO + r * 33 + j] = pack_bf16x2(l0, l1);
    }
    __syncthreads();

    int m0 = warp * 16;

    // ---- stage 1: C = attr @ W1^T (K=64, 3-term split bf16) ----
    float c[16][4];
    #pragma unroll
    for (int nt = 0; nt < 16; nt++)
        { c[nt][0] = 0.f; c[nt][1] = 0.f; c[nt][2] = 0.f; c[nt][3] = 0.f; }

    for (int kc = 0; kc < 4; kc++) {
        int w0 = kc * 8 + qc;
        int rA = (m0 + qr) * 33, rB = (m0 + qr + 8) * 33;
        uint32_t ah0 = sm[SW_AHI + rA + w0],     ah1 = sm[SW_AHI + rB + w0];
        uint32_t ah2 = sm[SW_AHI + rA + w0 + 4], ah3 = sm[SW_AHI + rB + w0 + 4];
        uint32_t al0 = sm[SW_ALO + rA + w0],     al1 = sm[SW_ALO + rB + w0];
        uint32_t al2 = sm[SW_ALO + rA + w0 + 4], al3 = sm[SW_ALO + rB + w0 + 4];
        #pragma unroll
        for (int nt = 0; nt < 16; nt++) {
            int fb = nt * 256 + kc * 64;
            uint32_t bh0 = sm[SW_W1HI + fb + lane], bh1 = sm[SW_W1HI + fb + 32 + lane];
            uint32_t bl0 = sm[SW_W1LO + fb + lane], bl1 = sm[SW_W1LO + fb + 32 + lane];
            mma_bf16(c[nt], ah0, ah1, ah2, ah3, bh0, bh1);
            mma_bf16(c[nt], ah0, ah1, ah2, ah3, bl0, bl1);
            mma_bf16(c[nt], al0, al1, al2, al3, bh0, bh1);
        }
    }

    // ---- epilogue 1: t = ssp(c + b1); split hi/lo into packed T (warp-local) ----
    #pragma unroll
    for (int nt = 0; nt < 16; nt++) {
        int col0 = nt * 8 + qc * 2;
        float2 bv = *(float2*)&smf[SW_B1 + col0];
        float t0 = sspf(c[nt][0] + bv.x), t1 = sspf(c[nt][1] + bv.y);
        float t2 = sspf(c[nt][2] + bv.x), t3 = sspf(c[nt][3] + bv.y);
        float h0, l0, h1, l1, h2, l2, h3, l3;
        bf16_split(t0, h0, l0); bf16_split(t1, h1, l1);
        bf16_split(t2, h2, l2); bf16_split(t3, h3, l3);
        int wi = nt * 4 + qc;
        int rA = (m0 + qr) * 65, rB = (m0 + qr + 8) * 65;
        sm[SW_THI + rA + wi] = pack_bf16x2(h0, h1);
        sm[SW_TLO + rA + wi] = pack_bf16x2(l0, l1);
        sm[SW_THI + rB + wi] = pack_bf16x2(h2, h3);
        sm[SW_TLO + rB + wi] = pack_bf16x2(l2, l3);
    }
    __syncwarp();

    // ---- stage 2: D = T @ W2^T (K=128, 3-term split bf16) ----
    float d[16][4];
    #pragma unroll
    for (int nt = 0; nt < 16; nt++)
        { d[nt][0] = 0.f; d[nt][1] = 0.f; d[nt][2] = 0.f; d[nt][3] = 0.f; }

    for (int kc = 0; kc < 8; kc++) {
        int w0 = kc * 8 + qc;
        int rA = (m0 + qr) * 65, rB = (m0 + qr + 8) * 65;
        uint32_t ah0 = sm[SW_THI + rA + w0],     ah1 = sm[SW_THI + rB + w0];
        uint32_t ah2 = sm[SW_THI + rA + w0 + 4], ah3 = sm[SW_THI + rB + w0 + 4];
        uint32_t al0 = sm[SW_TLO + rA + w0],     al1 = sm[SW_TLO + rB + w0];
        uint32_t al2 = sm[SW_TLO + rA + w0 + 4], al3 = sm[SW_TLO + rB + w0 + 4];
        #pragma unroll
        for (int nt = 0; nt < 16; nt++) {
            int fb = nt * 512 + kc * 64;
            uint32_t bh0 = sm[SW_W2HI + fb + lane], bh1 = sm[SW_W2HI + fb + 32 + lane];
            uint32_t bl0 = sm[SW_W2LO + fb + lane], bl1 = sm[SW_W2LO + fb + 32 + lane];
            mma_bf16(d[nt], ah0, ah1, ah2, ah3, bh0, bh1);
            mma_bf16(d[nt], ah0, ah1, ah2, ah3, bl0, bl1);
            mma_bf16(d[nt], al0, al1, al2, al3, bh0, bh1);
        }
    }

    // ---- epilogue 2: Wf=(d+b2)*cv; msg = h[src]*Wf; agg[dst] += msg ----
    {
        int r0 = m0 + qr, r1 = r0 + 8;
        float cv0 = smf[SW_CV + r0], cv1 = smf[SW_CV + r1];
        int s0 = ((int*)sm)[SW_SRC + r0], s1 = ((int*)sm)[SW_SRC + r1];
        int d0 = ((int*)sm)[SW_DST + r0], d1 = ((int*)sm)[SW_DST + r1];
        const float* h0p = h + (size_t)s0 * NF;
        const float* h1p = h + (size_t)s1 * NF;
        float* a0p = agg + (size_t)d0 * NF;
        float* a1p = agg + (size_t)d1 * NF;
        #pragma unroll
        for (int nt = 0; nt < 16; nt++) {
            int col0 = nt * 8 + qc * 2;
            float2 bv = *(float2*)&smf[SW_B2 + col0];
            float2 hv0 = *(const float2*)(h0p + col0);
            float m00 = (d[nt][0] + bv.x) * cv0 * hv0.x;
            float m01 = (d[nt][1] + bv.y) * cv0 * hv0.y;
            red_add_v2(a0p + col0, m00, m01);
            float2 hv1 = *(const float2*)(h1p + col0);
            float m10 = (d[nt][2] + bv.x) * cv1 * hv1.x;
            float m11 = (d[nt][3] + bv.y) * cv1 * hv1.y;
            red_add_v2(a1p + col0, m10, m11);
        }
    }
}

// =================================================================
// Row GEMM (CUDA cores), RB rows per warp — known-good 82us/call
// =================================================================
#define ROW_SMEM ((128 * 128 + 128) * 4)

__global__ __launch_bounds__(256)
void row_gemm_kernel(const float* __restrict__ X, const float* __restrict__ W,
                     const float* __restrict__ B, float* __restrict__ Y,
                     int N, int doSsp) {
    extern __shared__ float smg[];
    float* sWT = smg;
    float* sB  = smg + 128 * 128;

    int tid = threadIdx.x;
    for (int i = tid; i < 128 * 128; i += blockDim.x) {
        int f = i >> 7, j = i & 127;
        sWT[j * 128 + f] = W[i];
    }
    if (tid < 128) sB[tid] = B ? B[tid] : 0.f;
    __syncthreads();

    int lane = tid & 31, warp = tid >> 5;
    int gw = blockIdx.x * (blockDim.x >> 5) + warp;
    int tw = gridDim.x * (blockDim.x >> 5);
    float4 bv = ((const float4*)sB)[lane];
    u64 blo = pack2(bv.x, bv.y), bhi = pack2(bv.z, bv.w);

    int ngroups = (N + RB - 1) / RB;
    for (int g = gw; g < ngroups; g += tw) {
        int n0 = g * RB;
        float4 xv[RB];
        u64 acc0[RB], acc1[RB];
        #pragma unroll
        for (int r = 0; r < RB; r++) {
            int n = n0 + r;
            xv[r] = (n < N) ? *(const float4*)(X + (size_t)n * 128 + 4 * lane)
                            : make_float4(0.f, 0.f, 0.f, 0.f);
            acc0[r] = blo; acc1[r] = bhi;
        }
        #pragma unroll 2
        for (int s = 0; s < 32; s++) {
            const float* wp = sWT + (s * 4) * 128;
            ulonglong2 r0 = ((const ulonglong2*)(wp      ))[lane];
            ulonglong2 r1 = ((const ulonglong2*)(wp + 128))[lane];
            ulonglong2 r2 = ((const ulonglong2*)(wp + 256))[lane];
            ulonglong2 r3 = ((const ulonglong2*)(wp + 384))[lane];
            #pragma unroll
            for (int r = 0; r < RB; r++) {
                float x0 = __shfl_sync(0xffffffffu, xv[r].x, s);
                float x1 = __shfl_sync(0xffffffffu, xv[r].y, s);
                float x2 = __shfl_sync(0xffffffffu, xv[r].z, s);
                float x3 = __shfl_sync(0xffffffffu, xv[r].w, s);
                u64 a;
                a = dup2(x0); fma2(acc0[r], a, r0.x); fma2(acc1[r], a, r0.y);
                a = dup2(x1); fma2(acc0[r], a, r1.x); fma2(acc1[r], a, r1.y);
                a = dup2(x2); fma2(acc0[r], a, r2.x); fma2(acc1[r], a, r2.y);
                a = dup2(x3); fma2(acc0[r], a, r3.x); fma2(acc1[r], a, r3.y);
            }
        }
        #pragma unroll
        for (int r = 0; r < RB; r++) {
            int n = n0 + r;
            if (n >= N) break;
            float o0, o1, o2, o3;
            unpack2(acc0[r], o0, o1); unpack2(acc1[r], o2, o3);
            if (doSsp) { o0 = sspf(o0); o1 = sspf(o1); o2 = sspf(o2); o3 = sspf(o3); }
            *(float4*)(Y + (size_t)n * 128 + 4 * lane) = make_float4(o0, o1, o2, o3);
        }
    }
}

// =================================================================
extern "C" void kernel_launch(void* const* d_in, const int* in_sizes, int n_in,
                              void* d_out, int out_size) {
    const float* x    = (const float*)d_in[0];
    const int*   ei   = (const int*)  d_in[1];
    const float* ew   = (const float*)d_in[2];
    const float* attr = (const float*)d_in[3];
    const float* w1   = (const float*)d_in[4];
    const float* b1   = (const float*)d_in[5];
    const float* w2   = (const float*)d_in[6];
    const float* b2   = (const float*)d_in[7];
    const float* l1w  = (const float*)d_in[8];
    const float* l2w  = (const float*)d_in[9];
    const float* l2b  = (const float*)d_in[10];
    const float* lw   = (const float*)d_in[11];
    const float* lb   = (const float*)d_in[12];
    float* out = (float*)d_out;

    int N = in_sizes[0] / HIDDEN;
    int E = in_sizes[2];

    void *ph = nullptr, *pagg = nullptr, *pu = nullptr;
    cudaGetSymbolAddress(&ph,   g_h);
    cudaGetSymbolAddress(&pagg, g_agg);
    cudaGetSymbolAddress(&pu,   g_u);

    cudaFuncSetAttribute(row_gemm_kernel, cudaFuncAttributeMaxDynamicSharedMemorySize, ROW_SMEM);
    cudaFuncSetAttribute(edge_mma_kernel, cudaFuncAttributeMaxDynamicSharedMemorySize, EDGE_SMEM);

    cudaMemsetAsync(pagg, 0, (size_t)N * NF * sizeof(float));
    prep_weights_kernel<<<64, 256>>>(w1, w2);
    // h = x @ lin1_w^T
    row_gemm_kernel<<<625, 256, ROW_SMEM>>>(x, l1w, nullptr, (float*)ph, N, 0);
    // fused edge: filter MLP on tensor cores (mma.sync bf16 split) + CFConv + scatter
    int ntiles = (E + 127) / 128;
    edge_mma_kernel<<<ntiles, 256, EDGE_SMEM>>>((const float*)ph, ei, ew, attr,
                                                b1, b2, (float*)pagg, E);
    // u = ssp(agg @ lin2_w^T + lin2_b)
    row_gemm_kernel<<<625, 256, ROW_SMEM>>>((const float*)pagg, l2w, l2b, (float*)pu, N, 1);
    // out = u @ lin_w^T + lin_b
    row_gemm_kernel<<<625, 256, ROW_SMEM>>>((const float*)pu, lw, lb, out, N, 0);
}

// round 10
// speedup vs baseline: 2.7757x; 2.0377x over previous
#include <cuda_runtime.h>
#include <cuda_bf16.h>
#include <math.h>
#include <cstdint>

#define HIDDEN 128
#define NF 128
#define NG 50
#define MAXN 40000
#define NWARP 14
#define NTHREAD (NWARP * 32)

// ---------- helpers ----------
__device__ __forceinline__ void red_add_v2(float* p, float a, float b) {
    asm volatile("red.global.add.v2.f32 [%0], {%1,%2};" :: "l"(p), "f"(a), "f"(b) : "memory");
}
__device__ __forceinline__ float sspf(float x) {
    return fmaxf(x, 0.f) + __logf(0.5f * (1.0f + __expf(-fabsf(x))));
}
__device__ __forceinline__ void bf16_split(float v, float& hi, float& lo) {
    __nv_bfloat16 h = __float2bfloat16(v);
    hi = __bfloat162float(h);
    lo = v - hi;
}
__device__ __forceinline__ uint32_t pack_bf16x2(float v0, float v1) {
    __nv_bfloat162 p = __floats2bfloat162_rn(v0, v1);  // v0 -> low half
    return *(uint32_t*)&p;
}
// mma.sync m16n8k16 bf16 (baseline PTX — compiles for compute_103 family)
__device__ __forceinline__ void mma_bf16(float* c, uint32_t a0, uint32_t a1,
                                         uint32_t a2, uint32_t a3,
                                         uint32_t b0, uint32_t b1) {
    asm volatile(
        "mma.sync.aligned.m16n8k16.row.col.f32.bf16.bf16.f32 "
        "{%0,%1,%2,%3}, {%4,%5,%6,%7}, {%8,%9}, {%0,%1,%2,%3};"
        : "+f"(c[0]), "+f"(c[1]), "+f"(c[2]), "+f"(c[3])
        : "r"(a0), "r"(a1), "r"(a2), "r"(a3), "r"(b0), "r"(b1));
}

// ---------- scratch ----------
__device__ float g_h[(size_t)MAXN * NF];
__device__ float g_agg[(size_t)MAXN * NF];
__device__ float g_u[(size_t)MAXN * HIDDEN];
// edge weight frag blob: W1HI[4096] W1LO[4096] W2HI[8192] W2LO[8192] words
__device__ uint4 g_wblob[6144];
// lin weight frag blobs: 3 x (HI[8192] LO[8192]) words
__device__ uint4 g_linblob[3 * 4096];

// ================= prep: build mma B-fragment tables =================
// B frag (col-major operand for D = A @ W^T): n = nt*8 + lane/4,
// k = kc*16 + (lane%4)*2 + reg*8, packed pair (k, k+1)
__global__ void prep_weights_kernel(const float* __restrict__ w1,
                                    const float* __restrict__ w2,
                                    const float* __restrict__ l1w,
                                    const float* __restrict__ l2w,
                                    const float* __restrict__ lw) {
    uint32_t* blob = (uint32_t*)g_wblob;
    uint32_t* lblob = (uint32_t*)g_linblob;
    int tid = blockIdx.x * blockDim.x + threadIdx.x;
    int stride = gridDim.x * blockDim.x;
    // W1: 16 nt x 4 kc x 2 reg x 32 lanes = 4096 words
    for (int i = tid; i < 4096; i += stride) {
        int lane = i & 31, reg = (i >> 5) & 1, kc = (i >> 6) & 3, nt = i >> 8;
        int n = nt * 8 + (lane >> 2);
        int k0 = kc * 16 + (lane & 3) * 2 + reg * 8;
        float v0 = (k0 < NG)     ? w1[n * NG + k0]     : 0.f;
        float v1 = (k0 + 1 < NG) ? w1[n * NG + k0 + 1] : 0.f;
        float h0, l0, h1, l1;
        bf16_split(v0, h0, l0); bf16_split(v1, h1, l1);
        blob[i]        = pack_bf16x2(h0, h1);
        blob[4096 + i] = pack_bf16x2(l0, l1);
    }
    // W2 + 3 lin mats (all 128x128): 16 nt x 8 kc x 2 reg x 32 lanes = 8192 words
    for (int i = tid; i < 8192; i += stride) {
        int lane = i & 31, reg = (i >> 5) & 1, kc = (i >> 6) & 7, nt = i >> 9;
        int n = nt * 8 + (lane >> 2);
        int k0 = kc * 16 + (lane & 3) * 2 + reg * 8;
        float h0, l0, h1, l1;
        float v0 = w2[n * 128 + k0], v1 = w2[n * 128 + k0 + 1];
        bf16_split(v0, h0, l0); bf16_split(v1, h1, l1);
        blob[8192 + i]  = pack_bf16x2(h0, h1);
        blob[16384 + i] = pack_bf16x2(l0, l1);
        const float* mats[3] = {l1w, l2w, lw};
        #pragma unroll
        for (int m = 0; m < 3; m++) {
            v0 = mats[m][n * 128 + k0]; v1 = mats[m][n * 128 + k0 + 1];
            bf16_split(v0, h0, l0); bf16_split(v1, h1, l1);
            lblob[m * 16384 + i]        = pack_bf16x2(h0, h1);
            lblob[m * 16384 + 8192 + i] = pack_bf16x2(l0, l1);
        }
    }
}

// ================= persistent fused edge kernel =================
// smem (uint32 words): W[24576] | B1[128] | B2[128] | scratch 14 x 2176
#define ESM_B1   24576
#define ESM_B2   24704
#define ESM_SCR  24832
#define EDGE_SMEM ((ESM_SCR + NWARP * 2176) * 4)   /* 221184 B */

__global__ __launch_bounds__(NTHREAD, 1)
void edge_mma_kernel(const float* __restrict__ h, const int* __restrict__ ei,
                     const float* __restrict__ ew, const float* __restrict__ attr,
                     const float* __restrict__ b1, const float* __restrict__ b2,
                     float* __restrict__ agg, int E) {
    extern __shared__ uint32_t sm[];
    float* smf = (float*)sm;
    int tid = threadIdx.x;
    int warp = tid >> 5, lane = tid & 31;
    int qr = lane >> 2, qc = lane & 3;

    // one-time: weights + biases to smem
    {
        uint4* dst = (uint4*)sm;
        for (int i = tid; i < 6144; i += NTHREAD) dst[i] = g_wblob[i];
        if (tid < 128) { smf[ESM_B1 + tid] = b1[tid]; smf[ESM_B2 + tid] = b2[tid]; }
    }
    __syncthreads();

    uint32_t* hiB = sm + ESM_SCR + warp * 2176;   // 16 rows x stride 68
    uint32_t* loB = hiB + 1088;

    int ngroups = (E + 15) >> 4;
    for (int g = blockIdx.x * NWARP + warp; g < ngroups; g += gridDim.x * NWARP) {
        int e0 = g * 16;

        // ---- per-lane edge meta (lanes 0..15 own one edge each) ----
        int srcL = 0, dstL = 0; float cvL = 0.f;
        if (lane < 16) {
            int e = e0 + lane;
            bool valid = e < E;
            int ie = valid ? e : 0;
            srcL = ei[ie]; dstL = ei[E + ie];
            float w = ew[ie];
            cvL = valid ? 0.5f * (cospif(w * 0.1f) + 1.0f) : 0.f;
        }

        // ---- stage attr (16 rows x 25 pairs) into scratch, stride 68 ----
        #pragma unroll 4
        for (int r = 0; r < 16; r++) {
            int e = e0 + r;
            float2 v = make_float2(0.f, 0.f);
            if (lane < 25 && e < E) v = *(const float2*)(attr + (size_t)e * NG + 2 * lane);
            float h0, l0, h1, l1;
            bf16_split(v.x, h0, l0); bf16_split(v.y, h1, l1);
            hiB[r * 68 + lane] = pack_bf16x2(h0, h1);
            loB[r * 68 + lane] = pack_bf16x2(l0, l1);
        }
        __syncwarp();

        // ---- stage 1: C = attr @ W1^T (K=64, 3-term split) ----
        float c[16][4];
        #pragma unroll
        for (int nt = 0; nt < 16; nt++)
            { c[nt][0] = 0.f; c[nt][1] = 0.f; c[nt][2] = 0.f; c[nt][3] = 0.f; }
        #pragma unroll
        for (int kc = 0; kc < 4; kc++) {
            int w0 = kc * 8 + qc;
            int rA = qr * 68, rB = (qr + 8) * 68;
            uint32_t ah0 = hiB[rA + w0],     ah1 = hiB[rB + w0];
            uint32_t ah2 = hiB[rA + w0 + 4], ah3 = hiB[rB + w0 + 4];
            uint32_t al0 = loB[rA + w0],     al1 = loB[rB + w0];
            uint32_t al2 = loB[rA + w0 + 4], al3 = loB[rB + w0 + 4];
            #pragma unroll
            for (int nt = 0; nt < 16; nt++) {
                int fb = nt * 256 + kc * 64;
                uint32_t bh0 = sm[fb + lane],        bh1 = sm[fb + 32 + lane];
                uint32_t bl0 = sm[4096 + fb + lane], bl1 = sm[4096 + fb + 32 + lane];
                mma_bf16(c[nt], ah0, ah1, ah2, ah3, bh0, bh1);
                mma_bf16(c[nt], ah0, ah1, ah2, ah3, bl0, bl1);
                mma_bf16(c[nt], al0, al1, al2, al3, bh0, bh1);
            }
        }
        __syncwarp();

        // ---- epilogue 1: T = ssp(C + b1) -> scratch (overwrites attr) ----
        #pragma unroll
        for (int nt = 0; nt < 16; nt++) {
            int col0 = nt * 8 + qc * 2;
            float2 bv = *(float2*)&smf[ESM_B1 + col0];
            float t0 = sspf(c[nt][0] + bv.x), t1 = sspf(c[nt][1] + bv.y);
            float t2 = sspf(c[nt][2] + bv.x), t3 = sspf(c[nt][3] + bv.y);
            float h0, l0, h1, l1, h2, l2, h3, l3;
            bf16_split(t0, h0, l0); bf16_split(t1, h1, l1);
            bf16_split(t2, h2, l2); bf16_split(t3, h3, l3);
            int wi = nt * 4 + qc;
            int rA = qr * 68, rB = (qr + 8) * 68;
            hiB[rA + wi] = pack_bf16x2(h0, h1);
            loB[rA + wi] = pack_bf16x2(l0, l1);
            hiB[rB + wi] = pack_bf16x2(h2, h3);
            loB[rB + wi] = pack_bf16x2(l2, l3);
        }
        __syncwarp();

        // ---- stage 2: D = T @ W2^T (K=128, 3-term split) ----
        float d[16][4];
        #pragma unroll
        for (int nt = 0; nt < 16; nt++)
            { d[nt][0] = 0.f; d[nt][1] = 0.f; d[nt][2] = 0.f; d[nt][3] = 0.f; }
        #pragma unroll
        for (int kc = 0; kc < 8; kc++) {
            int w0 = kc * 8 + qc;
            int rA = qr * 68, rB = (qr + 8) * 68;
            uint32_t ah0 = hiB[rA + w0],     ah1 = hiB[rB + w0];
            uint32_t ah2 = hiB[rA + w0 + 4], ah3 = hiB[rB + w0 + 4];
            uint32_t al0 = loB[rA + w0],     al1 = loB[rB + w0];
            uint32_t al2 = loB[rA + w0 + 4], al3 = loB[rB + w0 + 4];
            #pragma unroll
            for (int nt = 0; nt < 16; nt++) {
                int fb = 8192 + nt * 512 + kc * 64;
                uint32_t bh0 = sm[fb + lane],        bh1 = sm[fb + 32 + lane];
                uint32_t bl0 = sm[8192 + fb + lane], bl1 = sm[8192 + fb + 32 + lane];
                mma_bf16(d[nt], ah0, ah1, ah2, ah3, bh0, bh1);
                mma_bf16(d[nt], ah0, ah1, ah2, ah3, bl0, bl1);
                mma_bf16(d[nt], al0, al1, al2, al3, bh0, bh1);
            }
        }

        // ---- epilogue 2: Wf=(D+b2)*cv; msg=h[src]*Wf; agg[dst]+=msg ----
        {
            unsigned full = 0xffffffffu;
            float cv0 = __shfl_sync(full, cvL, qr);
            float cv1 = __shfl_sync(full, cvL, qr + 8);
            int s0 = __shfl_sync(full, srcL, qr),     s1 = __shfl_sync(full, srcL, qr + 8);
            int d0 = __shfl_sync(full, dstL, qr),     d1 = __shfl_sync(full, dstL, qr + 8);
            const float* h0p = h + (size_t)s0 * NF;
            const float* h1p = h + (size_t)s1 * NF;
            float* a0p = agg + (size_t)d0 * NF;
            float* a1p = agg + (size_t)d1 * NF;
            #pragma unroll
            for (int nt = 0; nt < 16; nt++) {
                int col0 = nt * 8 + qc * 2;
                float2 bv = *(float2*)&smf[ESM_B2 + col0];
                float2 hv0 = *(const float2*)(h0p + col0);
                red_add_v2(a0p + col0, (d[nt][0] + bv.x) * cv0 * hv0.x,
                                        (d[nt][1] + bv.y) * cv0 * hv0.y);
                float2 hv1 = *(const float2*)(h1p + col0);
                red_add_v2(a1p + col0, (d[nt][2] + bv.x) * cv1 * hv1.x,
                                        (d[nt][3] + bv.y) * cv1 * hv1.y);
            }
        }
        __syncwarp();
    }
}

// ================= persistent mma row GEMM: Y = act(X @ W^T + b) =================
// smem words: W[16384] | BIAS[128] | scratch 14 x 2176
#define RSM_BIAS 16384
#define RSM_SCR  16512
#define ROW_SMEM ((RSM_SCR + NWARP * 2176) * 4)    /* 187904 B */

__global__ __launch_bounds__(NTHREAD, 1)
void row_mma_kernel(const float* __restrict__ X, const uint4* __restrict__ wblob,
                    const float* __restrict__ B, float* __restrict__ Y,
                    int N, int doSsp) {
    extern __shared__ uint32_t sm[];
    float* smf = (float*)sm;
    int tid = threadIdx.x;
    int warp = tid >> 5, lane = tid & 31;
    int qr = lane >> 2, qc = lane & 3;

    {
        uint4* dst = (uint4*)sm;
        for (int i = tid; i < 4096; i += NTHREAD) dst[i] = wblob[i];
        if (tid < 128) smf[RSM_BIAS + tid] = B ? B[tid] : 0.f;
    }
    __syncthreads();

    uint32_t* hiB = sm + RSM_SCR + warp * 2176;
    uint32_t* loB = hiB + 1088;

    int ngroups = (N + 15) >> 4;
    for (int g = blockIdx.x * NWARP + warp; g < ngroups; g += gridDim.x * NWARP) {
        int n0 = g * 16;
        // ---- stage X rows (16 x 64 pairs), stride 68 ----
        #pragma unroll 4
        for (int r = 0; r < 16; r++) {
            int n = n0 + r;
            float2 vA = make_float2(0.f, 0.f), vB = vA;
            if (n < N) {
                const float* xp = X + (size_t)n * 128;
                vA = *(const float2*)(xp + 2 * lane);
                vB = *(const float2*)(xp + 64 + 2 * lane);
            }
            float h0, l0, h1, l1;
            bf16_split(vA.x, h0, l0); bf16_split(vA.y, h1, l1);
            hiB[r * 68 + lane] = pack_bf16x2(h0, h1);
            loB[r * 68 + lane] = pack_bf16x2(l0, l1);
            bf16_split(vB.x, h0, l0); bf16_split(vB.y, h1, l1);
            hiB[r * 68 + 32 + lane] = pack_bf16x2(h0, h1);
            loB[r * 68 + 32 + lane] = pack_bf16x2(l0, l1);
        }
        __syncwarp();

        float c[16][4];
        #pragma unroll
        for (int nt = 0; nt < 16; nt++)
            { c[nt][0] = 0.f; c[nt][1] = 0.f; c[nt][2] = 0.f; c[nt][3] = 0.f; }
        #pragma unroll
        for (int kc = 0; kc < 8; kc++) {
            int w0 = kc * 8 + qc;
            int rA = qr * 68, rB = (qr + 8) * 68;
            uint32_t ah0 = hiB[rA + w0],     ah1 = hiB[rB + w0];
            uint32_t ah2 = hiB[rA + w0 + 4], ah3 = hiB[rB + w0 + 4];
            uint32_t al0 = loB[rA + w0],     al1 = loB[rB + w0];
            uint32_t al2 = loB[rA + w0 + 4], al3 = loB[rB + w0 + 4];
            #pragma unroll
            for (int nt = 0; nt < 16; nt++) {
                int fb = nt * 512 + kc * 64;
                uint32_t bh0 = sm[fb + lane],        bh1 = sm[fb + 32 + lane];
                uint32_t bl0 = sm[8192 + fb + lane], bl1 = sm[8192 + fb + 32 + lane];
                mma_bf16(c[nt], ah0, ah1, ah2, ah3, bh0, bh1);
                mma_bf16(c[nt], ah0, ah1, ah2, ah3, bl0, bl1);
                mma_bf16(c[nt], al0, al1, al2, al3, bh0, bh1);
            }
        }

        // ---- epilogue ----
        int nA = n0 + qr, nB = n0 + qr + 8;
        #pragma unroll
        for (int nt = 0; nt < 16; nt++) {
            int col0 = nt * 8 + qc * 2;
            float2 bv = *(float2*)&smf[RSM_BIAS + col0];
            float o0 = c[nt][0] + bv.x, o1 = c[nt][1] + bv.y;
            float o2 = c[nt][2] + bv.x, o3 = c[nt][3] + bv.y;
            if (doSsp) { o0 = sspf(o0); o1 = sspf(o1); o2 = sspf(o2); o3 = sspf(o3); }
            if (nA < N) *(float2*)(Y + (size_t)nA * 128 + col0) = make_float2(o0, o1);
            if (nB < N) *(float2*)(Y + (size_t)nB * 128 + col0) = make_float2(o2, o3);
        }
        __syncwarp();
    }
}

// =================================================================
extern "C" void kernel_launch(void* const* d_in, const int* in_sizes, int n_in,
                              void* d_out, int out_size) {
    const float* x    = (const float*)d_in[0];
    const int*   ei   = (const int*)  d_in[1];
    const float* ew   = (const float*)d_in[2];
    const float* attr = (const float*)d_in[3];
    const float* w1   = (const float*)d_in[4];
    const float* b1   = (const float*)d_in[5];
    const float* w2   = (const float*)d_in[6];
    const float* b2   = (const float*)d_in[7];
    const float* l1w  = (const float*)d_in[8];
    const float* l2w  = (const float*)d_in[9];
    const float* l2b  = (const float*)d_in[10];
    const float* lw   = (const float*)d_in[11];
    const float* lb   = (const float*)d_in[12];
    float* out = (float*)d_out;

    int N = in_sizes[0] / HIDDEN;
    int E = in_sizes[2];

    void *ph = nullptr, *pagg = nullptr, *pu = nullptr, *plb = nullptr;
    cudaGetSymbolAddress(&ph,   g_h);
    cudaGetSymbolAddress(&pagg, g_agg);
    cudaGetSymbolAddress(&pu,   g_u);
    cudaGetSymbolAddress(&plb,  g_linblob);
    const uint4* linblob = (const uint4*)plb;

    (void)cudaFuncSetAttribute(row_mma_kernel,  cudaFuncAttributeMaxDynamicSharedMemorySize, ROW_SMEM);
    (void)cudaFuncSetAttribute(edge_mma_kernel, cudaFuncAttributeMaxDynamicSharedMemorySize, EDGE_SMEM);

    cudaMemsetAsync(pagg, 0, (size_t)N * NF * sizeof(float));
    prep_weights_kernel<<<64, 256>>>(w1, w2, l1w, l2w, lw);
    // h = x @ lin1_w^T
    row_mma_kernel<<<148, NTHREAD, ROW_SMEM>>>(x, linblob + 0,    nullptr, (float*)ph, N, 0);
    // fused edge: filter MLP (mma.sync split-bf16) + CFConv + scatter, persistent
    edge_mma_kernel<<<148, NTHREAD, EDGE_SMEM>>>((const float*)ph, ei, ew, attr,
                                                 b1, b2, (float*)pagg, E);
    // u = ssp(agg @ lin2_w^T + lin2_b)
    row_mma_kernel<<<148, NTHREAD, ROW_SMEM>>>((const float*)pagg, linblob + 4096, l2b, (float*)pu, N, 1);
    // out = u @ lin_w^T + lin_b
    row_mma_kernel<<<148, NTHREAD, ROW_SMEM>>>((const float*)pu, linblob + 8192, lb, out, N, 0);
}

// round 11
// speedup vs baseline: 3.5251x; 1.2700x over previous
#include <cuda_runtime.h>
#include <cuda_bf16.h>
#include <cuda_fp16.h>
#include <math.h>
#include <cstdint>

#define HIDDEN 128
#define NF 128
#define NG 50
#define MAXN 40000
#define NWARP 14
#define NTHREAD (NWARP * 32)
#define NWARP_E 16
#define NTHREAD_E (NWARP_E * 32)

// ---------- helpers ----------
__device__ __forceinline__ void red_add_v4(float* p, float a, float b, float c, float d) {
    asm volatile("red.global.add.v4.f32 [%0], {%1,%2,%3,%4};"
                 :: "l"(p), "f"(a), "f"(b), "f"(c), "f"(d) : "memory");
}
__device__ __forceinline__ float sspf(float x) {
    return fmaxf(x, 0.f) + __logf(0.5f * (1.0f + __expf(-fabsf(x))));
}
__device__ __forceinline__ void bf16_split(float v, float& hi, float& lo) {
    __nv_bfloat16 h = __float2bfloat16(v);
    hi = __bfloat162float(h);
    lo = v - hi;
}
__device__ __forceinline__ uint32_t pack_bf16x2(float v0, float v1) {
    __nv_bfloat162 p = __floats2bfloat162_rn(v0, v1);
    return *(uint32_t*)&p;
}
__device__ __forceinline__ void h16_split(float v, float& hi, float& lo) {
    __half h = __float2half(v);
    hi = __half2float(h);
    lo = v - hi;
}
__device__ __forceinline__ uint32_t pack_h2(float v0, float v1) {
    __half2 p = __floats2half2_rn(v0, v1);   // v0 -> low half
    return *(uint32_t*)&p;
}
// bf16 mma (row kernels / prep path)
__device__ __forceinline__ void mma_bf16(float* c, uint32_t a0, uint32_t a1,
                                         uint32_t a2, uint32_t a3,
                                         uint32_t b0, uint32_t b1) {
    asm volatile(
        "mma.sync.aligned.m16n8k16.row.col.f32.bf16.bf16.f32 "
        "{%0,%1,%2,%3}, {%4,%5,%6,%7}, {%8,%9}, {%0,%1,%2,%3};"
        : "+f"(c[0]), "+f"(c[1]), "+f"(c[2]), "+f"(c[3])
        : "r"(a0), "r"(a1), "r"(a2), "r"(a3), "r"(b0), "r"(b1));
}
// fp16 mma (edge kernel)
__device__ __forceinline__ void mma_f16(float* c, uint32_t a0, uint32_t a1,
                                        uint32_t a2, uint32_t a3,
                                        uint32_t b0, uint32_t b1) {
    asm volatile(
        "mma.sync.aligned.m16n8k16.row.col.f32.f16.f16.f32 "
        "{%0,%1,%2,%3}, {%4,%5,%6,%7}, {%8,%9}, {%0,%1,%2,%3};"
        : "+f"(c[0]), "+f"(c[1]), "+f"(c[2]), "+f"(c[3])
        : "r"(a0), "r"(a1), "r"(a2), "r"(a3), "r"(b0), "r"(b1));
}

// ---------- scratch ----------
__device__ float g_h[(size_t)MAXN * NF];
__device__ float g_agg[(size_t)MAXN * NF];
__device__ float g_u[(size_t)MAXN * HIDDEN];
// edge fp16 frag blob: W1[4096] W2[8192] words = 48KB
__device__ uint4 g_wblob[6144];
// lin bf16 frag blobs: 3 x (HI[8192] LO[8192]) words
__device__ uint4 g_linblob[3 * 4096];

// ================= prep: build mma B-fragment tables =================
// B frag (col-major operand for D = A @ W^T): n = nt*8 + lane/4,
// k = kc*16 + (lane%4)*2 + reg*8, packed pair (k, k+1)
__global__ void prep_weights_kernel(const float* __restrict__ w1,
                                    const float* __restrict__ w2,
                                    const float* __restrict__ l1w,
                                    const float* __restrict__ l2w,
                                    const float* __restrict__ lw) {
    uint32_t* blob = (uint32_t*)g_wblob;
    uint32_t* lblob = (uint32_t*)g_linblob;
    int tid = blockIdx.x * blockDim.x + threadIdx.x;
    int stride = gridDim.x * blockDim.x;
    // W1 fp16: 16 nt x 4 kc x 2 reg x 32 lanes = 4096 words
    for (int i = tid; i < 4096; i += stride) {
        int lane = i & 31, reg = (i >> 5) & 1, kc = (i >> 6) & 3, nt = i >> 8;
        int n = nt * 8 + (lane >> 2);
        int k0 = kc * 16 + (lane & 3) * 2 + reg * 8;
        float v0 = (k0 < NG)     ? w1[n * NG + k0]     : 0.f;
        float v1 = (k0 + 1 < NG) ? w1[n * NG + k0 + 1] : 0.f;
        blob[i] = pack_h2(v0, v1);
    }
    // W2 fp16 (128x128): 16 nt x 8 kc x 2 reg x 32 lanes = 8192 words
    // + 3 lin mats bf16 split (row kernels)
    for (int i = tid; i < 8192; i += stride) {
        int lane = i & 31, reg = (i >> 5) & 1, kc = (i >> 6) & 7, nt = i >> 9;
        int n = nt * 8 + (lane >> 2);
        int k0 = kc * 16 + (lane & 3) * 2 + reg * 8;
        blob[4096 + i] = pack_h2(w2[n * 128 + k0], w2[n * 128 + k0 + 1]);
        const float* mats[3] = {l1w, l2w, lw};
        float h0, l0, h1, l1;
        #pragma unroll
        for (int m = 0; m < 3; m++) {
            float v0 = mats[m][n * 128 + k0], v1 = mats[m][n * 128 + k0 + 1];
            bf16_split(v0, h0, l0); bf16_split(v1, h1, l1);
            lblob[m * 16384 + i]        = pack_bf16x2(h0, h1);
            lblob[m * 16384 + 8192 + i] = pack_bf16x2(l0, l1);
        }
    }
}

// ================= persistent fused edge kernel (fp16 2-term) =================
// smem words: W1[4096] W2[8192] | B1[128] | B2[128] | scratch 16 x 2176
#define ESM_B1   12288
#define ESM_B2   12416
#define ESM_SCR  12544
#define EDGE_SMEM ((ESM_SCR + NWARP_E * 2176) * 4)   /* 189440 B */

__global__ __launch_bounds__(NTHREAD_E, 1)
void edge_mma_kernel(const float* __restrict__ h, const int* __restrict__ ei,
                     const float* __restrict__ ew, const float* __restrict__ attr,
                     const float* __restrict__ b1, const float* __restrict__ b2,
                     float* __restrict__ agg, int E) {
    extern __shared__ uint32_t sm[];
    float* smf = (float*)sm;
    int tid = threadIdx.x;
    int warp = tid >> 5, lane = tid & 31;
    int qr = lane >> 2, qc = lane & 3;

    // one-time: weights + biases to smem
    {
        uint4* dst = (uint4*)sm;
        for (int i = tid; i < 3072; i += NTHREAD_E) dst[i] = g_wblob[i];
        if (tid < 128) { smf[ESM_B1 + tid] = b1[tid]; smf[ESM_B2 + tid] = b2[tid]; }
    }
    __syncthreads();

    uint32_t* hiB = sm + ESM_SCR + warp * 2176;   // 16 rows x stride 68
    uint32_t* loB = hiB + 1088;

    int ngroups = (E + 15) >> 4;
    for (int g = blockIdx.x * NWARP_E + warp; g < ngroups; g += gridDim.x * NWARP_E) {
        int e0 = g * 16;

        // ---- per-lane edge meta (lanes 0..15 own one edge each) ----
        int srcL = 0, dstL = 0; float cvL = 0.f;
        if (lane < 16) {
            int e = e0 + lane;
            bool valid = e < E;
            int ie = valid ? e : 0;
            srcL = ei[ie]; dstL = ei[E + ie];
            float w = ew[ie];
            cvL = valid ? 0.5f * (cospif(w * 0.1f) + 1.0f) : 0.f;
        }

        // ---- stage attr (16 rows x 25 pairs) as fp16 hi/lo, stride 68 ----
        #pragma unroll 4
        for (int r = 0; r < 16; r++) {
            int e = e0 + r;
            float2 v = make_float2(0.f, 0.f);
            if (lane < 25 && e < E) v = *(const float2*)(attr + (size_t)e * NG + 2 * lane);
            float h0, l0, h1, l1;
            h16_split(v.x, h0, l0); h16_split(v.y, h1, l1);
            hiB[r * 68 + lane] = pack_h2(h0, h1);
            loB[r * 68 + lane] = pack_h2(l0, l1);
        }
        __syncwarp();

        // ---- stage 1: C = attr @ W1^T (K=64, A 2-term fp16, B hi only) ----
        float c[16][4];
        #pragma unroll
        for (int nt = 0; nt < 16; nt++)
            { c[nt][0] = 0.f; c[nt][1] = 0.f; c[nt][2] = 0.f; c[nt][3] = 0.f; }
        #pragma unroll
        for (int kc = 0; kc < 4; kc++) {
            int w0 = kc * 8 + qc;
            int rA = qr * 68, rB = (qr + 8) * 68;
            uint32_t ah0 = hiB[rA + w0],     ah1 = hiB[rB + w0];
            uint32_t ah2 = hiB[rA + w0 + 4], ah3 = hiB[rB + w0 + 4];
            uint32_t al0 = loB[rA + w0],     al1 = loB[rB + w0];
            uint32_t al2 = loB[rA + w0 + 4], al3 = loB[rB + w0 + 4];
            #pragma unroll
            for (int nt = 0; nt < 16; nt++) {
                int fb = nt * 256 + kc * 64;
                uint32_t bh0 = sm[fb + lane], bh1 = sm[fb + 32 + lane];
                mma_f16(c[nt], ah0, ah1, ah2, ah3, bh0, bh1);
                mma_f16(c[nt], al0, al1, al2, al3, bh0, bh1);
            }
        }
        __syncwarp();

        // ---- epilogue 1: T = ssp(C + b1) -> fp16 hi/lo scratch ----
        #pragma unroll
        for (int nt = 0; nt < 16; nt++) {
            int col0 = nt * 8 + qc * 2;
            float2 bv = *(float2*)&smf[ESM_B1 + col0];
            float t0 = sspf(c[nt][0] + bv.x), t1 = sspf(c[nt][1] + bv.y);
            float t2 = sspf(c[nt][2] + bv.x), t3 = sspf(c[nt][3] + bv.y);
            float h0, l0, h1, l1, h2, l2, h3, l3;
            h16_split(t0, h0, l0); h16_split(t1, h1, l1);
            h16_split(t2, h2, l2); h16_split(t3, h3, l3);
            int wi = nt * 4 + qc;
            int rA = qr * 68, rB = (qr + 8) * 68;
            hiB[rA + wi] = pack_h2(h0, h1);
            loB[rA + wi] = pack_h2(l0, l1);
            hiB[rB + wi] = pack_h2(h2, h3);
            loB[rB + wi] = pack_h2(l2, l3);
        }
        __syncwarp();

        // ---- stage 2: D = T @ W2^T (K=128, A 2-term fp16, B hi only) ----
        float d[16][4];
        #pragma unroll
        for (int nt = 0; nt < 16; nt++)
            { d[nt][0] = 0.f; d[nt][1] = 0.f; d[nt][2] = 0.f; d[nt][3] = 0.f; }
        #pragma unroll
        for (int kc = 0; kc < 8; kc++) {
            int w0 = kc * 8 + qc;
            int rA = qr * 68, rB = (qr + 8) * 68;
            uint32_t ah0 = hiB[rA + w0],     ah1 = hiB[rB + w0];
            uint32_t ah2 = hiB[rA + w0 + 4], ah3 = hiB[rB + w0 + 4];
            uint32_t al0 = loB[rA + w0],     al1 = loB[rB + w0];
            uint32_t al2 = loB[rA + w0 + 4], al3 = loB[rB + w0 + 4];
            #pragma unroll
            for (int nt = 0; nt < 16; nt++) {
                int fb = 4096 + nt * 512 + kc * 64;
                uint32_t bh0 = sm[fb + lane], bh1 = sm[fb + 32 + lane];
                mma_f16(d[nt], ah0, ah1, ah2, ah3, bh0, bh1);
                mma_f16(d[nt], al0, al1, al2, al3, bh0, bh1);
            }
        }

        // ---- epilogue 2 (transposed v4): Wf=(D+b2)*cv; msg=h[src]*Wf; agg[dst]+=msg ----
        {
            unsigned full = 0xffffffffu;
            int odd = lane & 1;
            int idx = qr + odd * 8;                 // edge row this lane owns post-transpose
            float cvM = __shfl_sync(full, cvL, idx);
            int sM = __shfl_sync(full, srcL, idx);
            int dM = __shfl_sync(full, dstL, idx);
            const float* hrow = h + (size_t)sM * NF;
            float* arow = agg + (size_t)dM * NF;
            int sub4 = (qc >> 1) * 4;
            #pragma unroll
            for (int nt = 0; nt < 16; nt++) {
                float sa = odd ? d[nt][0] : d[nt][2];
                float sb = odd ? d[nt][1] : d[nt][3];
                float ra = __shfl_xor_sync(full, sa, 1);
                float rb = __shfl_xor_sync(full, sb, 1);
                float v0 = odd ? ra : d[nt][0];
                float v1 = odd ? rb : d[nt][1];
                float v2 = odd ? d[nt][2] : ra;
                float v3 = odd ? d[nt][3] : rb;
                int basecol = nt * 8 + sub4;
                float4 bv = *(const float4*)&smf[ESM_B2 + basecol];
                float4 hv = *(const float4*)(hrow + basecol);
                red_add_v4(arow + basecol,
                           (v0 + bv.x) * cvM * hv.x, (v1 + bv.y) * cvM * hv.y,
                           (v2 + bv.z) * cvM * hv.z, (v3 + bv.w) * cvM * hv.w);
            }
        }
        __syncwarp();
    }
}

// ================= persistent mma row GEMM: Y = act(X @ W^T + b) =================
// smem words: W[16384] | BIAS[128] | scratch 14 x 2176
#define RSM_BIAS 16384
#define RSM_SCR  16512
#define ROW_SMEM ((RSM_SCR + NWARP * 2176) * 4)    /* 187904 B */

__global__ __launch_bounds__(NTHREAD, 1)
void row_mma_kernel(const float* __restrict__ X, const uint4* __restrict__ wblob,
                    const float* __restrict__ B, float* __restrict__ Y,
                    int N, int doSsp) {
    extern __shared__ uint32_t sm[];
    float* smf = (float*)sm;
    int tid = threadIdx.x;
    int warp = tid >> 5, lane = tid & 31;
    int qr = lane >> 2, qc = lane & 3;

    {
        uint4* dst = (uint4*)sm;
        for (int i = tid; i < 4096; i += NTHREAD) dst[i] = wblob[i];
        if (tid < 128) smf[RSM_BIAS + tid] = B ? B[tid] : 0.f;
    }
    __syncthreads();

    uint32_t* hiB = sm + RSM_SCR + warp * 2176;
    uint32_t* loB = hiB + 1088;

    int ngroups = (N + 15) >> 4;
    for (int g = blockIdx.x * NWARP + warp; g < ngroups; g += gridDim.x * NWARP) {
        int n0 = g * 16;
        // ---- stage X rows (16 x 64 pairs), stride 68 ----
        #pragma unroll 4
        for (int r = 0; r < 16; r++) {
            int n = n0 + r;
            float2 vA = make_float2(0.f, 0.f), vB = vA;
            if (n < N) {
                const float* xp = X + (size_t)n * 128;
                vA = *(const float2*)(xp + 2 * lane);
                vB = *(const float2*)(xp + 64 + 2 * lane);
            }
            float h0, l0, h1, l1;
            bf16_split(vA.x, h0, l0); bf16_split(vA.y, h1, l1);
            hiB[r * 68 + lane] = pack_bf16x2(h0, h1);
            loB[r * 68 + lane] = pack_bf16x2(l0, l1);
            bf16_split(vB.x, h0, l0); bf16_split(vB.y, h1, l1);
            hiB[r * 68 + 32 + lane] = pack_bf16x2(h0, h1);
            loB[r * 68 + 32 + lane] = pack_bf16x2(l0, l1);
        }
        __syncwarp();

        float c[16][4];
        #pragma unroll
        for (int nt = 0; nt < 16; nt++)
            { c[nt][0] = 0.f; c[nt][1] = 0.f; c[nt][2] = 0.f; c[nt][3] = 0.f; }
        #pragma unroll
        for (int kc = 0; kc < 8; kc++) {
            int w0 = kc * 8 + qc;
            int rA = qr * 68, rB = (qr + 8) * 68;
            uint32_t ah0 = hiB[rA + w0],     ah1 = hiB[rB + w0];
            uint32_t ah2 = hiB[rA + w0 + 4], ah3 = hiB[rB + w0 + 4];
            uint32_t al0 = loB[rA + w0],     al1 = loB[rB + w0];
            uint32_t al2 = loB[rA + w0 + 4], al3 = loB[rB + w0 + 4];
            #pragma unroll
            for (int nt = 0; nt < 16; nt++) {
                int fb = nt * 512 + kc * 64;
                uint32_t bh0 = sm[fb + lane],        bh1 = sm[fb + 32 + lane];
                uint32_t bl0 = sm[8192 + fb + lane], bl1 = sm[8192 + fb + 32 + lane];
                mma_bf16(c[nt], ah0, ah1, ah2, ah3, bh0, bh1);
                mma_bf16(c[nt], ah0, ah1, ah2, ah3, bl0, bl1);
                mma_bf16(c[nt], al0, al1, al2, al3, bh0, bh1);
            }
        }

        // ---- epilogue ----
        int nA = n0 + qr, nB = n0 + qr + 8;
        #pragma unroll
        for (int nt = 0; nt < 16; nt++) {
            int col0 = nt * 8 + qc * 2;
            float2 bv = *(float2*)&smf[RSM_BIAS + col0];
            float o0 = c[nt][0] + bv.x, o1 = c[nt][1] + bv.y;
            float o2 = c[nt][2] + bv.x, o3 = c[nt][3] + bv.y;
            if (doSsp) { o0 = sspf(o0); o1 = sspf(o1); o2 = sspf(o2); o3 = sspf(o3); }
            if (nA < N) *(float2*)(Y + (size_t)nA * 128 + col0) = make_float2(o0, o1);
            if (nB < N) *(float2*)(Y + (size_t)nB * 128 + col0) = make_float2(o2, o3);
        }
        __syncwarp();
    }
}

// =================================================================
extern "C" void kernel_launch(void* const* d_in, const int* in_sizes, int n_in,
                              void* d_out, int out_size) {
    const float* x    = (const float*)d_in[0];
    const int*   ei   = (const int*)  d_in[1];
    const float* ew   = (const float*)d_in[2];
    const float* attr = (const float*)d_in[3];
    const float* w1   = (const float*)d_in[4];
    const float* b1   = (const float*)d_in[5];
    const float* w2   = (const float*)d_in[6];
    const float* b2   = (const float*)d_in[7];
    const float* l1w  = (const float*)d_in[8];
    const float* l2w  = (const float*)d_in[9];
    const float* l2b  = (const float*)d_in[10];
    const float* lw   = (const float*)d_in[11];
    const float* lb   = (const float*)d_in[12];
    float* out = (float*)d_out;

    int N = in_sizes[0] / HIDDEN;
    int E = in_sizes[2];

    void *ph = nullptr, *pagg = nullptr, *pu = nullptr, *plb = nullptr;
    cudaGetSymbolAddress(&ph,   g_h);
    cudaGetSymbolAddress(&pagg, g_agg);
    cudaGetSymbolAddress(&pu,   g_u);
    cudaGetSymbolAddress(&plb,  g_linblob);
    const uint4* linblob = (const uint4*)plb;

    (void)cudaFuncSetAttribute(row_mma_kernel,  cudaFuncAttributeMaxDynamicSharedMemorySize, ROW_SMEM);
    (void)cudaFuncSetAttribute(edge_mma_kernel, cudaFuncAttributeMaxDynamicSharedMemorySize, EDGE_SMEM);

    cudaMemsetAsync(pagg, 0, (size_t)N * NF * sizeof(float));
    prep_weights_kernel<<<64, 256>>>(w1, w2, l1w, l2w, lw);
    // h = x @ lin1_w^T
    row_mma_kernel<<<148, NTHREAD, ROW_SMEM>>>(x, linblob + 0,    nullptr, (float*)ph, N, 0);
    // fused edge: filter MLP (mma.sync fp16 2-term) + CFConv + v4 scatter, persistent
    edge_mma_kernel<<<148, NTHREAD_E, EDGE_SMEM>>>((const float*)ph, ei, ew, attr,
                                                   b1, b2, (float*)pagg, E);
    // u = ssp(agg @ lin2_w^T + lin2_b)
    row_mma_kernel<<<148, NTHREAD, ROW_SMEM>>>((const float*)pagg, linblob + 4096, l2b, (float*)pu, N, 1);
    // out = u @ lin_w^T + lin_b
    row_mma_kernel<<<148, NTHREAD, ROW_SMEM>>>((const float*)pu, linblob + 8192, lb, out, N, 0);
}

// round 12
// speedup vs baseline: 3.6239x; 1.0281x over previous
#include <cuda_runtime.h>
#include <cuda_bf16.h>
#include <cuda_fp16.h>
#include <math.h>
#include <cstdint>

#define HIDDEN 128
#define NF 128
#define NG 50
#define MAXN 40000
#define NWARP 14
#define NTHREAD (NWARP * 32)
#define NWARP_E 16
#define NTHREAD_E (NWARP_E * 32)
#define NWARP_F 11
#define NTHREAD_F (NWARP_F * 32)

// ---------- helpers ----------
__device__ __forceinline__ void red_add_v4(float* p, float a, float b, float c, float d) {
    asm volatile("red.global.add.v4.f32 [%0], {%1,%2,%3,%4};"
                 :: "l"(p), "f"(a), "f"(b), "f"(c), "f"(d) : "memory");
}
__device__ __forceinline__ float sspf(float x) {
    return fmaxf(x, 0.f) + __logf(0.5f * (1.0f + __expf(-fabsf(x))));
}
__device__ __forceinline__ void bf16_split(float v, float& hi, float& lo) {
    __nv_bfloat16 h = __float2bfloat16(v);
    hi = __bfloat162float(h);
    lo = v - hi;
}
__device__ __forceinline__ uint32_t pack_bf16x2(float v0, float v1) {
    __nv_bfloat162 p = __floats2bfloat162_rn(v0, v1);
    return *(uint32_t*)&p;
}
__device__ __forceinline__ void h16_split(float v, float& hi, float& lo) {
    __half h = __float2half(v);
    hi = __half2float(h);
    lo = v - hi;
}
__device__ __forceinline__ uint32_t pack_h2(float v0, float v1) {
    __half2 p = __floats2half2_rn(v0, v1);   // v0 -> low half
    return *(uint32_t*)&p;
}
// bf16 mma (row/fused kernels)
__device__ __forceinline__ void mma_bf16(float* c, uint32_t a0, uint32_t a1,
                                         uint32_t a2, uint32_t a3,
                                         uint32_t b0, uint32_t b1) {
    asm volatile(
        "mma.sync.aligned.m16n8k16.row.col.f32.bf16.bf16.f32 "
        "{%0,%1,%2,%3}, {%4,%5,%6,%7}, {%8,%9}, {%0,%1,%2,%3};"
        : "+f"(c[0]), "+f"(c[1]), "+f"(c[2]), "+f"(c[3])
        : "r"(a0), "r"(a1), "r"(a2), "r"(a3), "r"(b0), "r"(b1));
}
// fp16 mma (edge kernel)
__device__ __forceinline__ void mma_f16(float* c, uint32_t a0, uint32_t a1,
                                        uint32_t a2, uint32_t a3,
                                        uint32_t b0, uint32_t b1) {
    asm volatile(
        "mma.sync.aligned.m16n8k16.row.col.f32.f16.f16.f32 "
        "{%0,%1,%2,%3}, {%4,%5,%6,%7}, {%8,%9}, {%0,%1,%2,%3};"
        : "+f"(c[0]), "+f"(c[1]), "+f"(c[2]), "+f"(c[3])
        : "r"(a0), "r"(a1), "r"(a2), "r"(a3), "r"(b0), "r"(b1));
}

// ---------- scratch ----------
__device__ float g_h[(size_t)MAXN * NF];
__device__ float g_agg[(size_t)MAXN * NF];
// edge fp16 frag blob: W1[4096] W2[8192] words = 48KB
__device__ uint4 g_wblob[6144];
// lin bf16 frag blobs: 3 x (HI[8192] LO[8192]) words
__device__ uint4 g_linblob[3 * 4096];

// ================= prep: build mma B-fragment tables =================
// B frag (col-major operand for D = A @ W^T): n = nt*8 + lane/4,
// k = kc*16 + (lane%4)*2 + reg*8, packed pair (k, k+1)
__global__ void prep_weights_kernel(const float* __restrict__ w1,
                                    const float* __restrict__ w2,
                                    const float* __restrict__ l1w,
                                    const float* __restrict__ l2w,
                                    const float* __restrict__ lw) {
    uint32_t* blob = (uint32_t*)g_wblob;
    uint32_t* lblob = (uint32_t*)g_linblob;
    int tid = blockIdx.x * blockDim.x + threadIdx.x;
    int stride = gridDim.x * blockDim.x;
    // W1 fp16: 16 nt x 4 kc x 2 reg x 32 lanes = 4096 words
    for (int i = tid; i < 4096; i += stride) {
        int lane = i & 31, reg = (i >> 5) & 1, kc = (i >> 6) & 3, nt = i >> 8;
        int n = nt * 8 + (lane >> 2);
        int k0 = kc * 16 + (lane & 3) * 2 + reg * 8;
        float v0 = (k0 < NG)     ? w1[n * NG + k0]     : 0.f;
        float v1 = (k0 + 1 < NG) ? w1[n * NG + k0 + 1] : 0.f;
        blob[i] = pack_h2(v0, v1);
    }
    // W2 fp16 (128x128): 16 nt x 8 kc x 2 reg x 32 lanes = 8192 words
    // + 3 lin mats bf16 split (row/fused kernels)
    for (int i = tid; i < 8192; i += stride) {
        int lane = i & 31, reg = (i >> 5) & 1, kc = (i >> 6) & 7, nt = i >> 9;
        int n = nt * 8 + (lane >> 2);
        int k0 = kc * 16 + (lane & 3) * 2 + reg * 8;
        blob[4096 + i] = pack_h2(w2[n * 128 + k0], w2[n * 128 + k0 + 1]);
        const float* mats[3] = {l1w, l2w, lw};
        float h0, l0, h1, l1;
        #pragma unroll
        for (int m = 0; m < 3; m++) {
            float v0 = mats[m][n * 128 + k0], v1 = mats[m][n * 128 + k0 + 1];
            bf16_split(v0, h0, l0); bf16_split(v1, h1, l1);
            lblob[m * 16384 + i]        = pack_bf16x2(h0, h1);
            lblob[m * 16384 + 8192 + i] = pack_bf16x2(l0, l1);
        }
    }
}

// ================= persistent fused edge kernel (fp16 2-term) =================
// smem words: W1[4096] W2[8192] | B1[128] | B2[128] | scratch 16 x 2176
#define ESM_B1   12288
#define ESM_B2   12416
#define ESM_SCR  12544
#define EDGE_SMEM ((ESM_SCR + NWARP_E * 2176) * 4)   /* 189440 B */

__global__ __launch_bounds__(NTHREAD_E, 1)
void edge_mma_kernel(const float* __restrict__ h, const int* __restrict__ ei,
                     const float* __restrict__ ew, const float* __restrict__ attr,
                     const float* __restrict__ b1, const float* __restrict__ b2,
                     float* __restrict__ agg, int E) {
    extern __shared__ uint32_t sm[];
    float* smf = (float*)sm;
    int tid = threadIdx.x;
    int warp = tid >> 5, lane = tid & 31;
    int qr = lane >> 2, qc = lane & 3;

    // one-time: weights + biases to smem
    {
        uint4* dst = (uint4*)sm;
        for (int i = tid; i < 3072; i += NTHREAD_E) dst[i] = g_wblob[i];
        if (tid < 128) { smf[ESM_B1 + tid] = b1[tid]; smf[ESM_B2 + tid] = b2[tid]; }
    }
    __syncthreads();

    uint32_t* hiB = sm + ESM_SCR + warp * 2176;   // 16 rows x stride 68
    uint32_t* loB = hiB + 1088;

    int ngroups = (E + 15) >> 4;
    for (int g = blockIdx.x * NWARP_E + warp; g < ngroups; g += gridDim.x * NWARP_E) {
        int e0 = g * 16;

        // ---- per-lane edge meta (lanes 0..15 own one edge each) ----
        int srcL = 0, dstL = 0; float cvL = 0.f;
        if (lane < 16) {
            int e = e0 + lane;
            bool valid = e < E;
            int ie = valid ? e : 0;
            srcL = ei[ie]; dstL = ei[E + ie];
            float w = ew[ie];
            cvL = valid ? 0.5f * (cospif(w * 0.1f) + 1.0f) : 0.f;
        }

        // ---- stage attr (16 rows x 25 pairs) as fp16 hi/lo, stride 68 ----
        #pragma unroll 4
        for (int r = 0; r < 16; r++) {
            int e = e0 + r;
            float2 v = make_float2(0.f, 0.f);
            if (lane < 25 && e < E) v = *(const float2*)(attr + (size_t)e * NG + 2 * lane);
            float h0, l0, h1, l1;
            h16_split(v.x, h0, l0); h16_split(v.y, h1, l1);
            hiB[r * 68 + lane] = pack_h2(h0, h1);
            loB[r * 68 + lane] = pack_h2(l0, l1);
        }
        __syncwarp();

        // ---- stage 1: C = attr @ W1^T (K=64, A 2-term fp16, B hi only) ----
        float c[16][4];
        #pragma unroll
        for (int nt = 0; nt < 16; nt++)
            { c[nt][0] = 0.f; c[nt][1] = 0.f; c[nt][2] = 0.f; c[nt][3] = 0.f; }
        #pragma unroll
        for (int kc = 0; kc < 4; kc++) {
            int w0 = kc * 8 + qc;
            int rA = qr * 68, rB = (qr + 8) * 68;
            uint32_t ah0 = hiB[rA + w0],     ah1 = hiB[rB + w0];
            uint32_t ah2 = hiB[rA + w0 + 4], ah3 = hiB[rB + w0 + 4];
            uint32_t al0 = loB[rA + w0],     al1 = loB[rB + w0];
            uint32_t al2 = loB[rA + w0 + 4], al3 = loB[rB + w0 + 4];
            #pragma unroll
            for (int nt = 0; nt < 16; nt++) {
                int fb = nt * 256 + kc * 64;
                uint32_t bh0 = sm[fb + lane], bh1 = sm[fb + 32 + lane];
                mma_f16(c[nt], ah0, ah1, ah2, ah3, bh0, bh1);
                mma_f16(c[nt], al0, al1, al2, al3, bh0, bh1);
            }
        }
        __syncwarp();

        // ---- epilogue 1: T = ssp(C + b1) -> fp16 hi/lo scratch ----
        #pragma unroll
        for (int nt = 0; nt < 16; nt++) {
            int col0 = nt * 8 + qc * 2;
            float2 bv = *(float2*)&smf[ESM_B1 + col0];
            float t0 = sspf(c[nt][0] + bv.x), t1 = sspf(c[nt][1] + bv.y);
            float t2 = sspf(c[nt][2] + bv.x), t3 = sspf(c[nt][3] + bv.y);
            float h0, l0, h1, l1, h2, l2, h3, l3;
            h16_split(t0, h0, l0); h16_split(t1, h1, l1);
            h16_split(t2, h2, l2); h16_split(t3, h3, l3);
            int wi = nt * 4 + qc;
            int rA = qr * 68, rB = (qr + 8) * 68;
            hiB[rA + wi] = pack_h2(h0, h1);
            loB[rA + wi] = pack_h2(l0, l1);
            hiB[rB + wi] = pack_h2(h2, h3);
            loB[rB + wi] = pack_h2(l2, l3);
        }
        __syncwarp();

        // ---- stage 2: D = T @ W2^T (K=128, A 2-term fp16, B hi only) ----
        float d[16][4];
        #pragma unroll
        for (int nt = 0; nt < 16; nt++)
            { d[nt][0] = 0.f; d[nt][1] = 0.f; d[nt][2] = 0.f; d[nt][3] = 0.f; }
        #pragma unroll
        for (int kc = 0; kc < 8; kc++) {
            int w0 = kc * 8 + qc;
            int rA = qr * 68, rB = (qr + 8) * 68;
            uint32_t ah0 = hiB[rA + w0],     ah1 = hiB[rB + w0];
            uint32_t ah2 = hiB[rA + w0 + 4], ah3 = hiB[rB + w0 + 4];
            uint32_t al0 = loB[rA + w0],     al1 = loB[rB + w0];
            uint32_t al2 = loB[rA + w0 + 4], al3 = loB[rB + w0 + 4];
            #pragma unroll
            for (int nt = 0; nt < 16; nt++) {
                int fb = 4096 + nt * 512 + kc * 64;
                uint32_t bh0 = sm[fb + lane], bh1 = sm[fb + 32 + lane];
                mma_f16(d[nt], ah0, ah1, ah2, ah3, bh0, bh1);
                mma_f16(d[nt], al0, al1, al2, al3, bh0, bh1);
            }
        }

        // ---- epilogue 2 (transposed v4): Wf=(D+b2)*cv; msg=h[src]*Wf; agg[dst]+=msg ----
        {
            unsigned full = 0xffffffffu;
            int odd = lane & 1;
            int idx = qr + odd * 8;                 // edge row this lane owns post-transpose
            float cvM = __shfl_sync(full, cvL, idx);
            int sM = __shfl_sync(full, srcL, idx);
            int dM = __shfl_sync(full, dstL, idx);
            const float* hrow = h + (size_t)sM * NF;
            float* arow = agg + (size_t)dM * NF;
            int sub4 = (qc >> 1) * 4;
            #pragma unroll
            for (int nt = 0; nt < 16; nt++) {
                float sa = odd ? d[nt][0] : d[nt][2];
                float sb = odd ? d[nt][1] : d[nt][3];
                float ra = __shfl_xor_sync(full, sa, 1);
                float rb = __shfl_xor_sync(full, sb, 1);
                float v0 = odd ? ra : d[nt][0];
                float v1 = odd ? rb : d[nt][1];
                float v2 = odd ? d[nt][2] : ra;
                float v3 = odd ? d[nt][3] : rb;
                int basecol = nt * 8 + sub4;
                float4 bv = *(const float4*)&smf[ESM_B2 + basecol];
                float4 hv = *(const float4*)(hrow + basecol);
                red_add_v4(arow + basecol,
                           (v0 + bv.x) * cvM * hv.x, (v1 + bv.y) * cvM * hv.y,
                           (v2 + bv.z) * cvM * hv.z, (v3 + bv.w) * cvM * hv.w);
            }
        }
        __syncwarp();
    }
}

// ================= persistent mma row GEMM: Y = X @ W^T (bf16 3-term) =================
// smem words: W[16384] | BIAS[128] | scratch 14 x 2176
#define RSM_BIAS 16384
#define RSM_SCR  16512
#define ROW_SMEM ((RSM_SCR + NWARP * 2176) * 4)    /* 187904 B */

__global__ __launch_bounds__(NTHREAD, 1)
void row_mma_kernel(const float* __restrict__ X, const uint4* __restrict__ wblob,
                    const float* __restrict__ B, float* __restrict__ Y,
                    int N, int doSsp) {
    extern __shared__ uint32_t sm[];
    float* smf = (float*)sm;
    int tid = threadIdx.x;
    int warp = tid >> 5, lane = tid & 31;
    int qr = lane >> 2, qc = lane & 3;

    {
        uint4* dst = (uint4*)sm;
        for (int i = tid; i < 4096; i += NTHREAD) dst[i] = wblob[i];
        if (tid < 128) smf[RSM_BIAS + tid] = B ? B[tid] : 0.f;
    }
    __syncthreads();

    uint32_t* hiB = sm + RSM_SCR + warp * 2176;
    uint32_t* loB = hiB + 1088;

    int ngroups = (N + 15) >> 4;
    for (int g = blockIdx.x * NWARP + warp; g < ngroups; g += gridDim.x * NWARP) {
        int n0 = g * 16;
        // ---- stage X rows (16 x 64 pairs), stride 68 ----
        #pragma unroll 4
        for (int r = 0; r < 16; r++) {
            int n = n0 + r;
            float2 vA = make_float2(0.f, 0.f), vB = vA;
            if (n < N) {
                const float* xp = X + (size_t)n * 128;
                vA = *(const float2*)(xp + 2 * lane);
                vB = *(const float2*)(xp + 64 + 2 * lane);
            }
            float h0, l0, h1, l1;
            bf16_split(vA.x, h0, l0); bf16_split(vA.y, h1, l1);
            hiB[r * 68 + lane] = pack_bf16x2(h0, h1);
            loB[r * 68 + lane] = pack_bf16x2(l0, l1);
            bf16_split(vB.x, h0, l0); bf16_split(vB.y, h1, l1);
            hiB[r * 68 + 32 + lane] = pack_bf16x2(h0, h1);
            loB[r * 68 + 32 + lane] = pack_bf16x2(l0, l1);
        }
        __syncwarp();

        float c[16][4];
        #pragma unroll
        for (int nt = 0; nt < 16; nt++)
            { c[nt][0] = 0.f; c[nt][1] = 0.f; c[nt][2] = 0.f; c[nt][3] = 0.f; }
        #pragma unroll
        for (int kc = 0; kc < 8; kc++) {
            int w0 = kc * 8 + qc;
            int rA = qr * 68, rB = (qr + 8) * 68;
            uint32_t ah0 = hiB[rA + w0],     ah1 = hiB[rB + w0];
            uint32_t ah2 = hiB[rA + w0 + 4], ah3 = hiB[rB + w0 + 4];
            uint32_t al0 = loB[rA + w0],     al1 = loB[rB + w0];
            uint32_t al2 = loB[rA + w0 + 4], al3 = loB[rB + w0 + 4];
            #pragma unroll
            for (int nt = 0; nt < 16; nt++) {
                int fb = nt * 512 + kc * 64;
                uint32_t bh0 = sm[fb + lane],        bh1 = sm[fb + 32 + lane];
                uint32_t bl0 = sm[8192 + fb + lane], bl1 = sm[8192 + fb + 32 + lane];
                mma_bf16(c[nt], ah0, ah1, ah2, ah3, bh0, bh1);
                mma_bf16(c[nt], ah0, ah1, ah2, ah3, bl0, bl1);
                mma_bf16(c[nt], al0, al1, al2, al3, bh0, bh1);
            }
        }

        // ---- epilogue ----
        int nA = n0 + qr, nB = n0 + qr + 8;
        #pragma unroll
        for (int nt = 0; nt < 16; nt++) {
            int col0 = nt * 8 + qc * 2;
            float2 bv = *(float2*)&smf[RSM_BIAS + col0];
            float o0 = c[nt][0] + bv.x, o1 = c[nt][1] + bv.y;
            float o2 = c[nt][2] + bv.x, o3 = c[nt][3] + bv.y;
            if (doSsp) { o0 = sspf(o0); o1 = sspf(o1); o2 = sspf(o2); o3 = sspf(o3); }
            if (nA < N) *(float2*)(Y + (size_t)nA * 128 + col0) = make_float2(o0, o1);
            if (nB < N) *(float2*)(Y + (size_t)nB * 128 + col0) = make_float2(o2, o3);
        }
        __syncwarp();
    }
}

// ================= fused output kernel: out = ssp(agg@l2w^T + l2b) @ lw^T + lb =================
// smem words: W2blob[16384] | W3blob[16384] | B2[128] | B3[128] | scratch 11 x 2176
#define FSM_W3   16384
#define FSM_B2   32768
#define FSM_B3   32896
#define FSM_SCR  33024
#define FUSE_SMEM ((FSM_SCR + NWARP_F * 2176) * 4)   /* 227840 B */

__global__ __launch_bounds__(NTHREAD_F, 1)
void fused_out_kernel(const float* __restrict__ X, const uint4* __restrict__ w2blob,
                      const uint4* __restrict__ w3blob,
                      const float* __restrict__ B2, const float* __restrict__ B3,
                      float* __restrict__ Y, int N) {
    extern __shared__ uint32_t sm[];
    float* smf = (float*)sm;
    int tid = threadIdx.x;
    int warp = tid >> 5, lane = tid & 31;
    int qr = lane >> 2, qc = lane & 3;

    {
        uint4* dst = (uint4*)sm;
        for (int i = tid; i < 4096; i += NTHREAD_F) dst[i] = w2blob[i];
        for (int i = tid; i < 4096; i += NTHREAD_F) dst[4096 + i] = w3blob[i];
        if (tid < 128) { smf[FSM_B2 + tid] = B2[tid]; smf[FSM_B3 + tid] = B3[tid]; }
    }
    __syncthreads();

    uint32_t* hiB = sm + FSM_SCR + warp * 2176;
    uint32_t* loB = hiB + 1088;

    int ngroups = (N + 15) >> 4;
    for (int g = blockIdx.x * NWARP_F + warp; g < ngroups; g += gridDim.x * NWARP_F) {
        int n0 = g * 16;
        // ---- stage X rows (16 x 64 pairs), stride 68 ----
        #pragma unroll 4
        for (int r = 0; r < 16; r++) {
            int n = n0 + r;
            float2 vA = make_float2(0.f, 0.f), vB = vA;
            if (n < N) {
                const float* xp = X + (size_t)n * 128;
                vA = *(const float2*)(xp + 2 * lane);
                vB = *(const float2*)(xp + 64 + 2 * lane);
            }
            float h0, l0, h1, l1;
            bf16_split(vA.x, h0, l0); bf16_split(vA.y, h1, l1);
            hiB[r * 68 + lane] = pack_bf16x2(h0, h1);
            loB[r * 68 + lane] = pack_bf16x2(l0, l1);
            bf16_split(vB.x, h0, l0); bf16_split(vB.y, h1, l1);
            hiB[r * 68 + 32 + lane] = pack_bf16x2(h0, h1);
            loB[r * 68 + 32 + lane] = pack_bf16x2(l0, l1);
        }
        __syncwarp();

        float c[16][4];
        // ---- stage 1: C = X @ l2w^T (bf16 3-term) ----
        #pragma unroll
        for (int nt = 0; nt < 16; nt++)
            { c[nt][0] = 0.f; c[nt][1] = 0.f; c[nt][2] = 0.f; c[nt][3] = 0.f; }
        #pragma unroll
        for (int kc = 0; kc < 8; kc++) {
            int w0 = kc * 8 + qc;
            int rA = qr * 68, rB = (qr + 8) * 68;
            uint32_t ah0 = hiB[rA + w0],     ah1 = hiB[rB + w0];
            uint32_t ah2 = hiB[rA + w0 + 4], ah3 = hiB[rB + w0 + 4];
            uint32_t al0 = loB[rA + w0],     al1 = loB[rB + w0];
            uint32_t al2 = loB[rA + w0 + 4], al3 = loB[rB + w0 + 4];
            #pragma unroll
            for (int nt = 0; nt < 16; nt++) {
                int fb = nt * 512 + kc * 64;
                uint32_t bh0 = sm[fb + lane],        bh1 = sm[fb + 32 + lane];
                uint32_t bl0 = sm[8192 + fb + lane], bl1 = sm[8192 + fb + 32 + lane];
                mma_bf16(c[nt], ah0, ah1, ah2, ah3, bh0, bh1);
                mma_bf16(c[nt], ah0, ah1, ah2, ah3, bl0, bl1);
                mma_bf16(c[nt], al0, al1, al2, al3, bh0, bh1);
            }
        }
        __syncwarp();

        // ---- epilogue 1: T = ssp(C + l2b) -> bf16 hi/lo scratch ----
        #pragma unroll
        for (int nt = 0; nt < 16; nt++) {
            int col0 = nt * 8 + qc * 2;
            float2 bv = *(float2*)&smf[FSM_B2 + col0];
            float t0 = sspf(c[nt][0] + bv.x), t1 = sspf(c[nt][1] + bv.y);
            float t2 = sspf(c[nt][2] + bv.x), t3 = sspf(c[nt][3] + bv.y);
            float h0, l0, h1, l1, h2, l2, h3, l3;
            bf16_split(t0, h0, l0); bf16_split(t1, h1, l1);
            bf16_split(t2, h2, l2); bf16_split(t3, h3, l3);
            int wi = nt * 4 + qc;
            int rA = qr * 68, rB = (qr + 8) * 68;
            hiB[rA + wi] = pack_bf16x2(h0, h1);
            loB[rA + wi] = pack_bf16x2(l0, l1);
            hiB[rB + wi] = pack_bf16x2(h2, h3);
            loB[rB + wi] = pack_bf16x2(l2, l3);
        }
        __syncwarp();

        // ---- stage 2: C = T @ lw^T (bf16 3-term) ----
        #pragma unroll
        for (int nt = 0; nt < 16; nt++)
            { c[nt][0] = 0.f; c[nt][1] = 0.f; c[nt][2] = 0.f; c[nt][3] = 0.f; }
        #pragma unroll
        for (int kc = 0; kc < 8; kc++) {
            int w0 = kc * 8 + qc;
            int rA = qr * 68, rB = (qr + 8) * 68;
            uint32_t ah0 = hiB[rA + w0],     ah1 = hiB[rB + w0];
            uint32_t ah2 = hiB[rA + w0 + 4], ah3 = hiB[rB + w0 + 4];
            uint32_t al0 = loB[rA + w0],     al1 = loB[rB + w0];
            uint32_t al2 = loB[rA + w0 + 4], al3 = loB[rB + w0 + 4];
            #pragma unroll
            for (int nt = 0; nt < 16; nt++) {
                int fb = FSM_W3 + nt * 512 + kc * 64;
                uint32_t bh0 = sm[fb + lane],        bh1 = sm[fb + 32 + lane];
                uint32_t bl0 = sm[8192 + fb + lane], bl1 = sm[8192 + fb + 32 + lane];
                mma_bf16(c[nt], ah0, ah1, ah2, ah3, bh0, bh1);
                mma_bf16(c[nt], ah0, ah1, ah2, ah3, bl0, bl1);
                mma_bf16(c[nt], al0, al1, al2, al3, bh0, bh1);
            }
        }

        // ---- epilogue 2: out = C + lb ----
        int nA = n0 + qr, nB = n0 + qr + 8;
        #pragma unroll
        for (int nt = 0; nt < 16; nt++) {
            int col0 = nt * 8 + qc * 2;
            float2 bv = *(float2*)&smf[FSM_B3 + col0];
            if (nA < N) *(float2*)(Y + (size_t)nA * 128 + col0)
                = make_float2(c[nt][0] + bv.x, c[nt][1] + bv.y);
            if (nB < N) *(float2*)(Y + (size_t)nB * 128 + col0)
                = make_float2(c[nt][2] + bv.x, c[nt][3] + bv.y);
        }
        __syncwarp();
    }
}

// =================================================================
extern "C" void kernel_launch(void* const* d_in, const int* in_sizes, int n_in,
                              void* d_out, int out_size) {
    const float* x    = (const float*)d_in[0];
    const int*   ei   = (const int*)  d_in[1];
    const float* ew   = (const float*)d_in[2];
    const float* attr = (const float*)d_in[3];
    const float* w1   = (const float*)d_in[4];
    const float* b1   = (const float*)d_in[5];
    const float* w2   = (const float*)d_in[6];
    const float* b2   = (const float*)d_in[7];
    const float* l1w  = (const float*)d_in[8];
    const float* l2w  = (const float*)d_in[9];
    const float* l2b  = (const float*)d_in[10];
    const float* lw   = (const float*)d_in[11];
    const float* lb   = (const float*)d_in[12];
    float* out = (float*)d_out;

    int N = in_sizes[0] / HIDDEN;
    int E = in_sizes[2];

    void *ph = nullptr, *pagg = nullptr, *plb = nullptr;
    cudaGetSymbolAddress(&ph,   g_h);
    cudaGetSymbolAddress(&pagg, g_agg);
    cudaGetSymbolAddress(&plb,  g_linblob);
    const uint4* linblob = (const uint4*)plb;

    (void)cudaFuncSetAttribute(row_mma_kernel,  cudaFuncAttributeMaxDynamicSharedMemorySize, ROW_SMEM);
    (void)cudaFuncSetAttribute(edge_mma_kernel, cudaFuncAttributeMaxDynamicSharedMemorySize, EDGE_SMEM);
    (void)cudaFuncSetAttribute(fused_out_kernel, cudaFuncAttributeMaxDynamicSharedMemorySize, FUSE_SMEM);

    cudaMemsetAsync(pagg, 0, (size_t)N * NF * sizeof(float));
    prep_weights_kernel<<<64, 256>>>(w1, w2, l1w, l2w, lw);
    // h = x @ lin1_w^T
    row_mma_kernel<<<148, NTHREAD, ROW_SMEM>>>(x, linblob + 0, nullptr, (float*)ph, N, 0);
    // fused edge: filter MLP (mma.sync fp16 2-term) + CFConv + v4 scatter, persistent
    edge_mma_kernel<<<148, NTHREAD_E, EDGE_SMEM>>>((const float*)ph, ei, ew, attr,
                                                   b1, b2, (float*)pagg, E);
    // out = ssp(agg @ lin2_w^T + l2b) @ lin_w^T + lb   (fused, no u round-trip)
    fused_out_kernel<<<148, NTHREAD_F, FUSE_SMEM>>>((const float*)pagg,
                                                    linblob + 4096, linblob + 8192,
                                                    l2b, lb, out, N);
}

// round 13
// speedup vs baseline: 4.3281x; 1.1943x over previous
#include <cuda_runtime.h>
#include <cuda_bf16.h>
#include <cuda_fp16.h>
#include <math.h>
#include <cstdint>

#define HIDDEN 128
#define NF 128
#define NG 50
#define MAXN 40000
#define NWARP 14
#define NTHREAD (NWARP * 32)
#define NWARP_E 16
#define NTHREAD_E (NWARP_E * 32)
#define NWARP_F 11
#define NTHREAD_F (NWARP_F * 32)

// ---------- helpers ----------
__device__ __forceinline__ void red_add_v4(float* p, float a, float b, float c, float d) {
    asm volatile("red.global.add.v4.f32 [%0], {%1,%2,%3,%4};"
                 :: "l"(p), "f"(a), "f"(b), "f"(c), "f"(d) : "memory");
}
__device__ __forceinline__ float sspf(float x) {
    return fmaxf(x, 0.f) + __logf(0.5f * (1.0f + __expf(-fabsf(x))));
}
__device__ __forceinline__ void h16_split(float v, float& hi, float& lo) {
    __half h = __float2half(v);
    hi = __half2float(h);
    lo = v - hi;
}
__device__ __forceinline__ uint32_t pack_h2(float v0, float v1) {
    __half2 p = __floats2half2_rn(v0, v1);   // v0 -> low half
    return *(uint32_t*)&p;
}
// fp16 mma
__device__ __forceinline__ void mma_f16(float* c, uint32_t a0, uint32_t a1,
                                        uint32_t a2, uint32_t a3,
                                        uint32_t b0, uint32_t b1) {
    asm volatile(
        "mma.sync.aligned.m16n8k16.row.col.f32.f16.f16.f32 "
        "{%0,%1,%2,%3}, {%4,%5,%6,%7}, {%8,%9}, {%0,%1,%2,%3};"
        : "+f"(c[0]), "+f"(c[1]), "+f"(c[2]), "+f"(c[3])
        : "r"(a0), "r"(a1), "r"(a2), "r"(a3), "r"(b0), "r"(b1));
}

// ---------- scratch ----------
__device__ float g_h[(size_t)MAXN * NF];
__device__ float g_agg[(size_t)MAXN * NF];
// edge fp16 frag blob: W1[4096] W2[8192] words = 48KB
__device__ uint4 g_wblob[6144];
// lin fp16 frag blobs: 3 x 8192 words = 96KB total
__device__ uint4 g_linblob[3 * 2048];

// ================= prep: build mma B-fragment tables (all fp16) =================
// B frag (col-major operand for D = A @ W^T): n = nt*8 + lane/4,
// k = kc*16 + (lane%4)*2 + reg*8, packed pair (k, k+1)
__global__ void prep_weights_kernel(const float* __restrict__ w1,
                                    const float* __restrict__ w2,
                                    const float* __restrict__ l1w,
                                    const float* __restrict__ l2w,
                                    const float* __restrict__ lw) {
    uint32_t* blob = (uint32_t*)g_wblob;
    uint32_t* lblob = (uint32_t*)g_linblob;
    int tid = blockIdx.x * blockDim.x + threadIdx.x;
    int stride = gridDim.x * blockDim.x;
    // W1 fp16: 16 nt x 4 kc x 2 reg x 32 lanes = 4096 words
    for (int i = tid; i < 4096; i += stride) {
        int lane = i & 31, reg = (i >> 5) & 1, kc = (i >> 6) & 3, nt = i >> 8;
        int n = nt * 8 + (lane >> 2);
        int k0 = kc * 16 + (lane & 3) * 2 + reg * 8;
        float v0 = (k0 < NG)     ? w1[n * NG + k0]     : 0.f;
        float v1 = (k0 + 1 < NG) ? w1[n * NG + k0 + 1] : 0.f;
        blob[i] = pack_h2(v0, v1);
    }
    // W2 + 3 lin mats (128x128) fp16: 16 nt x 8 kc x 2 reg x 32 lanes = 8192 words each
    for (int i = tid; i < 8192; i += stride) {
        int lane = i & 31, reg = (i >> 5) & 1, kc = (i >> 6) & 7, nt = i >> 9;
        int n = nt * 8 + (lane >> 2);
        int k0 = kc * 16 + (lane & 3) * 2 + reg * 8;
        blob[4096 + i] = pack_h2(w2[n * 128 + k0], w2[n * 128 + k0 + 1]);
        lblob[i]         = pack_h2(l1w[n * 128 + k0], l1w[n * 128 + k0 + 1]);
        lblob[8192 + i]  = pack_h2(l2w[n * 128 + k0], l2w[n * 128 + k0 + 1]);
        lblob[16384 + i] = pack_h2(lw[n * 128 + k0],  lw[n * 128 + k0 + 1]);
    }
}

// ================= persistent fused edge kernel =================
// stage1: A 1-term fp16 (attr); stage2: A 2-term fp16; B 1-term fp16 both
// smem words: W1[4096] W2[8192] | B1[128] | B2[128] | scratch 16 x 2176
#define ESM_B1   12288
#define ESM_B2   12416
#define ESM_SCR  12544
#define EDGE_SMEM ((ESM_SCR + NWARP_E * 2176) * 4)   /* 189440 B */

__global__ __launch_bounds__(NTHREAD_E, 1)
void edge_mma_kernel(const float* __restrict__ h, const int* __restrict__ ei,
                     const float* __restrict__ ew, const float* __restrict__ attr,
                     const float* __restrict__ b1, const float* __restrict__ b2,
                     float* __restrict__ agg, int E) {
    extern __shared__ uint32_t sm[];
    float* smf = (float*)sm;
    int tid = threadIdx.x;
    int warp = tid >> 5, lane = tid & 31;
    int qr = lane >> 2, qc = lane & 3;

    // one-time: weights + biases to smem
    {
        uint4* dst = (uint4*)sm;
        for (int i = tid; i < 3072; i += NTHREAD_E) dst[i] = g_wblob[i];
        if (tid < 128) { smf[ESM_B1 + tid] = b1[tid]; smf[ESM_B2 + tid] = b2[tid]; }
    }
    __syncthreads();

    uint32_t* hiB = sm + ESM_SCR + warp * 2176;   // 16 rows x stride 68
    uint32_t* loB = hiB + 1088;

    int ngroups = (E + 15) >> 4;
    for (int g = blockIdx.x * NWARP_E + warp; g < ngroups; g += gridDim.x * NWARP_E) {
        int e0 = g * 16;

        // ---- per-lane edge meta (lanes 0..15 own one edge each) ----
        int srcL = 0, dstL = 0; float cvL = 0.f;
        if (lane < 16) {
            int e = e0 + lane;
            bool valid = e < E;
            int ie = valid ? e : 0;
            srcL = ei[ie]; dstL = ei[E + ie];
            float w = ew[ie];
            cvL = valid ? 0.5f * (cospif(w * 0.1f) + 1.0f) : 0.f;
        }

        // ---- stage attr (16 rows x 25 pairs) as fp16 (1-term), stride 68 ----
        #pragma unroll 4
        for (int r = 0; r < 16; r++) {
            int e = e0 + r;
            float2 v = make_float2(0.f, 0.f);
            if (lane < 25 && e < E) v = *(const float2*)(attr + (size_t)e * NG + 2 * lane);
            hiB[r * 68 + lane] = pack_h2(v.x, v.y);
        }
        __syncwarp();

        // ---- stage 1: C = attr @ W1^T (K=64, A 1-term, B 1-term) ----
        float c[16][4];
        #pragma unroll
        for (int nt = 0; nt < 16; nt++)
            { c[nt][0] = 0.f; c[nt][1] = 0.f; c[nt][2] = 0.f; c[nt][3] = 0.f; }
        #pragma unroll
        for (int kc = 0; kc < 4; kc++) {
            int w0 = kc * 8 + qc;
            int rA = qr * 68, rB = (qr + 8) * 68;
            uint32_t ah0 = hiB[rA + w0],     ah1 = hiB[rB + w0];
            uint32_t ah2 = hiB[rA + w0 + 4], ah3 = hiB[rB + w0 + 4];
            #pragma unroll
            for (int nt = 0; nt < 16; nt++) {
                int fb = nt * 256 + kc * 64;
                uint32_t bh0 = sm[fb + lane], bh1 = sm[fb + 32 + lane];
                mma_f16(c[nt], ah0, ah1, ah2, ah3, bh0, bh1);
            }
        }
        __syncwarp();

        // ---- epilogue 1: T = ssp(C + b1) -> fp16 hi/lo scratch ----
        #pragma unroll
        for (int nt = 0; nt < 16; nt++) {
            int col0 = nt * 8 + qc * 2;
            float2 bv = *(float2*)&smf[ESM_B1 + col0];
            float t0 = sspf(c[nt][0] + bv.x), t1 = sspf(c[nt][1] + bv.y);
            float t2 = sspf(c[nt][2] + bv.x), t3 = sspf(c[nt][3] + bv.y);
            float h0, l0, h1, l1, h2, l2, h3, l3;
            h16_split(t0, h0, l0); h16_split(t1, h1, l1);
            h16_split(t2, h2, l2); h16_split(t3, h3, l3);
            int wi = nt * 4 + qc;
            int rA = qr * 68, rB = (qr + 8) * 68;
            hiB[rA + wi] = pack_h2(h0, h1);
            loB[rA + wi] = pack_h2(l0, l1);
            hiB[rB + wi] = pack_h2(h2, h3);
            loB[rB + wi] = pack_h2(l2, l3);
        }
        __syncwarp();

        // ---- stage 2: D = T @ W2^T (K=128, A 2-term fp16, B 1-term) ----
        float d[16][4];
        #pragma unroll
        for (int nt = 0; nt < 16; nt++)
            { d[nt][0] = 0.f; d[nt][1] = 0.f; d[nt][2] = 0.f; d[nt][3] = 0.f; }
        #pragma unroll
        for (int kc = 0; kc < 8; kc++) {
            int w0 = kc * 8 + qc;
            int rA = qr * 68, rB = (qr + 8) * 68;
            uint32_t ah0 = hiB[rA + w0],     ah1 = hiB[rB + w0];
            uint32_t ah2 = hiB[rA + w0 + 4], ah3 = hiB[rB + w0 + 4];
            uint32_t al0 = loB[rA + w0],     al1 = loB[rB + w0];
            uint32_t al2 = loB[rA + w0 + 4], al3 = loB[rB + w0 + 4];
            #pragma unroll
            for (int nt = 0; nt < 16; nt++) {
                int fb = 4096 + nt * 512 + kc * 64;
                uint32_t bh0 = sm[fb + lane], bh1 = sm[fb + 32 + lane];
                mma_f16(d[nt], ah0, ah1, ah2, ah3, bh0, bh1);
                mma_f16(d[nt], al0, al1, al2, al3, bh0, bh1);
            }
        }

        // ---- epilogue 2 (transposed v4): Wf=(D+b2)*cv; msg=h[src]*Wf; agg[dst]+=msg ----
        {
            unsigned full = 0xffffffffu;
            int odd = lane & 1;
            int idx = qr + odd * 8;                 // edge row this lane owns post-transpose
            float cvM = __shfl_sync(full, cvL, idx);
            int sM = __shfl_sync(full, srcL, idx);
            int dM = __shfl_sync(full, dstL, idx);
            const float* hrow = h + (size_t)sM * NF;
            float* arow = agg + (size_t)dM * NF;
            int sub4 = (qc >> 1) * 4;
            #pragma unroll
            for (int nt = 0; nt < 16; nt++) {
                float sa = odd ? d[nt][0] : d[nt][2];
                float sb = odd ? d[nt][1] : d[nt][3];
                float ra = __shfl_xor_sync(full, sa, 1);
                float rb = __shfl_xor_sync(full, sb, 1);
                float v0 = odd ? ra : d[nt][0];
                float v1 = odd ? rb : d[nt][1];
                float v2 = odd ? d[nt][2] : ra;
                float v3 = odd ? d[nt][3] : rb;
                int basecol = nt * 8 + sub4;
                float4 bv = *(const float4*)&smf[ESM_B2 + basecol];
                float4 hv = *(const float4*)(hrow + basecol);
                red_add_v4(arow + basecol,
                           (v0 + bv.x) * cvM * hv.x, (v1 + bv.y) * cvM * hv.y,
                           (v2 + bv.z) * cvM * hv.z, (v3 + bv.w) * cvM * hv.w);
            }
        }
        __syncwarp();
    }
}

// ================= persistent mma row GEMM (fp16 2-term A, 1-term B) =================
// smem words: W[8192] | BIAS[128] | scratch 14 x 2176
#define RSM_BIAS 8192
#define RSM_SCR  8320
#define ROW_SMEM ((RSM_SCR + NWARP * 2176) * 4)    /* 155136 B */

__global__ __launch_bounds__(NTHREAD, 1)
void row_mma_kernel(const float* __restrict__ X, const uint4* __restrict__ wblob,
                    const float* __restrict__ B, float* __restrict__ Y,
                    int N, int doSsp) {
    extern __shared__ uint32_t sm[];
    float* smf = (float*)sm;
    int tid = threadIdx.x;
    int warp = tid >> 5, lane = tid & 31;
    int qr = lane >> 2, qc = lane & 3;

    {
        uint4* dst = (uint4*)sm;
        for (int i = tid; i < 2048; i += NTHREAD) dst[i] = wblob[i];
        if (tid < 128) smf[RSM_BIAS + tid] = B ? B[tid] : 0.f;
    }
    __syncthreads();

    uint32_t* hiB = sm + RSM_SCR + warp * 2176;
    uint32_t* loB = hiB + 1088;

    int ngroups = (N + 15) >> 4;
    for (int g = blockIdx.x * NWARP + warp; g < ngroups; g += gridDim.x * NWARP) {
        int n0 = g * 16;
        // ---- stage X rows (16 x 64 pairs) fp16 hi/lo, stride 68 ----
        #pragma unroll 4
        for (int r = 0; r < 16; r++) {
            int n = n0 + r;
            float2 vA = make_float2(0.f, 0.f), vB = vA;
            if (n < N) {
                const float* xp = X + (size_t)n * 128;
                vA = *(const float2*)(xp + 2 * lane);
                vB = *(const float2*)(xp + 64 + 2 * lane);
            }
            float h0, l0, h1, l1;
            h16_split(vA.x, h0, l0); h16_split(vA.y, h1, l1);
            hiB[r * 68 + lane] = pack_h2(h0, h1);
            loB[r * 68 + lane] = pack_h2(l0, l1);
            h16_split(vB.x, h0, l0); h16_split(vB.y, h1, l1);
            hiB[r * 68 + 32 + lane] = pack_h2(h0, h1);
            loB[r * 68 + 32 + lane] = pack_h2(l0, l1);
        }
        __syncwarp();

        float c[16][4];
        #pragma unroll
        for (int nt = 0; nt < 16; nt++)
            { c[nt][0] = 0.f; c[nt][1] = 0.f; c[nt][2] = 0.f; c[nt][3] = 0.f; }
        #pragma unroll
        for (int kc = 0; kc < 8; kc++) {
            int w0 = kc * 8 + qc;
            int rA = qr * 68, rB = (qr + 8) * 68;
            uint32_t ah0 = hiB[rA + w0],     ah1 = hiB[rB + w0];
            uint32_t ah2 = hiB[rA + w0 + 4], ah3 = hiB[rB + w0 + 4];
            uint32_t al0 = loB[rA + w0],     al1 = loB[rB + w0];
            uint32_t al2 = loB[rA + w0 + 4], al3 = loB[rB + w0 + 4];
            #pragma unroll
            for (int nt = 0; nt < 16; nt++) {
                int fb = nt * 512 + kc * 64;
                uint32_t bh0 = sm[fb + lane], bh1 = sm[fb + 32 + lane];
                mma_f16(c[nt], ah0, ah1, ah2, ah3, bh0, bh1);
                mma_f16(c[nt], al0, al1, al2, al3, bh0, bh1);
            }
        }

        // ---- epilogue ----
        int nA = n0 + qr, nB = n0 + qr + 8;
        #pragma unroll
        for (int nt = 0; nt < 16; nt++) {
            int col0 = nt * 8 + qc * 2;
            float2 bv = *(float2*)&smf[RSM_BIAS + col0];
            float o0 = c[nt][0] + bv.x, o1 = c[nt][1] + bv.y;
            float o2 = c[nt][2] + bv.x, o3 = c[nt][3] + bv.y;
            if (doSsp) { o0 = sspf(o0); o1 = sspf(o1); o2 = sspf(o2); o3 = sspf(o3); }
            if (nA < N) *(float2*)(Y + (size_t)nA * 128 + col0) = make_float2(o0, o1);
            if (nB < N) *(float2*)(Y + (size_t)nB * 128 + col0) = make_float2(o2, o3);
        }
        __syncwarp();
    }
}

// ================= fused output kernel (fp16): out = ssp(agg@l2w^T + l2b) @ lw^T + lb =================
// smem words: W2[8192] | W3[8192] | B2[128] | B3[128] | scratch 11 x 2176
#define FSM_W3   8192
#define FSM_B2   16384
#define FSM_B3   16512
#define FSM_SCR  16640
#define FUSE_SMEM ((FSM_SCR + NWARP_F * 2176) * 4)   /* 162304 B */

__global__ __launch_bounds__(NTHREAD_F, 1)
void fused_out_kernel(const float* __restrict__ X, const uint4* __restrict__ w2blob,
                      const uint4* __restrict__ w3blob,
                      const float* __restrict__ B2, const float* __restrict__ B3,
                      float* __restrict__ Y, int N) {
    extern __shared__ uint32_t sm[];
    float* smf = (float*)sm;
    int tid = threadIdx.x;
    int warp = tid >> 5, lane = tid & 31;
    int qr = lane >> 2, qc = lane & 3;

    {
        uint4* dst = (uint4*)sm;
        for (int i = tid; i < 2048; i += NTHREAD_F) dst[i] = w2blob[i];
        for (int i = tid; i < 2048; i += NTHREAD_F) dst[2048 + i] = w3blob[i];
        if (tid < 128) { smf[FSM_B2 + tid] = B2[tid]; smf[FSM_B3 + tid] = B3[tid]; }
    }
    __syncthreads();

    uint32_t* hiB = sm + FSM_SCR + warp * 2176;
    uint32_t* loB = hiB + 1088;

    int ngroups = (N + 15) >> 4;
    for (int g = blockIdx.x * NWARP_F + warp; g < ngroups; g += gridDim.x * NWARP_F) {
        int n0 = g * 16;
        // ---- stage X rows (16 x 64 pairs) fp16 hi/lo, stride 68 ----
        #pragma unroll 4
        for (int r = 0; r < 16; r++) {
            int n = n0 + r;
            float2 vA = make_float2(0.f, 0.f), vB = vA;
            if (n < N) {
                const float* xp = X + (size_t)n * 128;
                vA = *(const float2*)(xp + 2 * lane);
                vB = *(const float2*)(xp + 64 + 2 * lane);
            }
            float h0, l0, h1, l1;
            h16_split(vA.x, h0, l0); h16_split(vA.y, h1, l1);
            hiB[r * 68 + lane] = pack_h2(h0, h1);
            loB[r * 68 + lane] = pack_h2(l0, l1);
            h16_split(vB.x, h0, l0); h16_split(vB.y, h1, l1);
            hiB[r * 68 + 32 + lane] = pack_h2(h0, h1);
            loB[r * 68 + 32 + lane] = pack_h2(l0, l1);
        }
        __syncwarp();

        float c[16][4];
        // ---- stage 1: C = X @ l2w^T (fp16 2-term A, 1-term B) ----
        #pragma unroll
        for (int nt = 0; nt < 16; nt++)
            { c[nt][0] = 0.f; c[nt][1] = 0.f; c[nt][2] = 0.f; c[nt][3] = 0.f; }
        #pragma unroll
        for (int kc = 0; kc < 8; kc++) {
            int w0 = kc * 8 + qc;
            int rA = qr * 68, rB = (qr + 8) * 68;
            uint32_t ah0 = hiB[rA + w0],     ah1 = hiB[rB + w0];
            uint32_t ah2 = hiB[rA + w0 + 4], ah3 = hiB[rB + w0 + 4];
            uint32_t al0 = loB[rA + w0],     al1 = loB[rB + w0];
            uint32_t al2 = loB[rA + w0 + 4], al3 = loB[rB + w0 + 4];
            #pragma unroll
            for (int nt = 0; nt < 16; nt++) {
                int fb = nt * 512 + kc * 64;
                uint32_t bh0 = sm[fb + lane], bh1 = sm[fb + 32 + lane];
                mma_f16(c[nt], ah0, ah1, ah2, ah3, bh0, bh1);
                mma_f16(c[nt], al0, al1, al2, al3, bh0, bh1);
            }
        }
        __syncwarp();

        // ---- epilogue 1: T = ssp(C + l2b) -> fp16 hi/lo scratch ----
        #pragma unroll
        for (int nt = 0; nt < 16; nt++) {
            int col0 = nt * 8 + qc * 2;
            float2 bv = *(float2*)&smf[FSM_B2 + col0];
            float t0 = sspf(c[nt][0] + bv.x), t1 = sspf(c[nt][1] + bv.y);
            float t2 = sspf(c[nt][2] + bv.x), t3 = sspf(c[nt][3] + bv.y);
            float h0, l0, h1, l1, h2, l2, h3, l3;
            h16_split(t0, h0, l0); h16_split(t1, h1, l1);
            h16_split(t2, h2, l2); h16_split(t3, h3, l3);
            int wi = nt * 4 + qc;
            int rA = qr * 68, rB = (qr + 8) * 68;
            hiB[rA + wi] = pack_h2(h0, h1);
            loB[rA + wi] = pack_h2(l0, l1);
            hiB[rB + wi] = pack_h2(h2, h3);
            loB[rB + wi] = pack_h2(l2, l3);
        }
        __syncwarp();

        // ---- stage 2: C = T @ lw^T (fp16 2-term A, 1-term B) ----
        #pragma unroll
        for (int nt = 0; nt < 16; nt++)
            { c[nt][0] = 0.f; c[nt][1] = 0.f; c[nt][2] = 0.f; c[nt][3] = 0.f; }
        #pragma unroll
        for (int kc = 0; kc < 8; kc++) {
            int w0 = kc * 8 + qc;
            int rA = qr * 68, rB = (qr + 8) * 68;
            uint32_t ah0 = hiB[rA + w0],     ah1 = hiB[rB + w0];
            uint32_t ah2 = hiB[rA + w0 + 4], ah3 = hiB[rB + w0 + 4];
            uint32_t al0 = loB[rA + w0],     al1 = loB[rB + w0];
            uint32_t al2 = loB[rA + w0 + 4], al3 = loB[rB + w0 + 4];
            #pragma unroll
            for (int nt = 0; nt < 16; nt++) {
                int fb = FSM_W3 + nt * 512 + kc * 64;
                uint32_t bh0 = sm[fb + lane], bh1 = sm[fb + 32 + lane];
                mma_f16(c[nt], ah0, ah1, ah2, ah3, bh0, bh1);
                mma_f16(c[nt], al0, al1, al2, al3, bh0, bh1);
            }
        }

        // ---- epilogue 2: out = C + lb ----
        int nA = n0 + qr, nB = n0 + qr + 8;
        #pragma unroll
        for (int nt = 0; nt < 16; nt++) {
            int col0 = nt * 8 + qc * 2;
            float2 bv = *(float2*)&smf[FSM_B3 + col0];
            if (nA < N) *(float2*)(Y + (size_t)nA * 128 + col0)
                = make_float2(c[nt][0] + bv.x, c[nt][1] + bv.y);
            if (nB < N) *(float2*)(Y + (size_t)nB * 128 + col0)
                = make_float2(c[nt][2] + bv.x, c[nt][3] + bv.y);
        }
        __syncwarp();
    }
}

// =================================================================
extern "C" void kernel_launch(void* const* d_in, const int* in_sizes, int n_in,
                              void* d_out, int out_size) {
    const float* x    = (const float*)d_in[0];
    const int*   ei   = (const int*)  d_in[1];
    const float* ew   = (const float*)d_in[2];
    const float* attr = (const float*)d_in[3];
    const float* w1   = (const float*)d_in[4];
    const float* b1   = (const float*)d_in[5];
    const float* w2   = (const float*)d_in[6];
    const float* b2   = (const float*)d_in[7];
    const float* l1w  = (const float*)d_in[8];
    const float* l2w  = (const float*)d_in[9];
    const float* l2b  = (const float*)d_in[10];
    const float* lw   = (const float*)d_in[11];
    const float* lb   = (const float*)d_in[12];
    float* out = (float*)d_out;

    int N = in_sizes[0] / HIDDEN;
    int E = in_sizes[2];

    void *ph = nullptr, *pagg = nullptr, *plb = nullptr;
    cudaGetSymbolAddress(&ph,   g_h);
    cudaGetSymbolAddress(&pagg, g_agg);
    cudaGetSymbolAddress(&plb,  g_linblob);
    const uint4* linblob = (const uint4*)plb;

    (void)cudaFuncSetAttribute(row_mma_kernel,   cudaFuncAttributeMaxDynamicSharedMemorySize, ROW_SMEM);
    (void)cudaFuncSetAttribute(edge_mma_kernel,  cudaFuncAttributeMaxDynamicSharedMemorySize, EDGE_SMEM);
    (void)cudaFuncSetAttribute(fused_out_kernel, cudaFuncAttributeMaxDynamicSharedMemorySize, FUSE_SMEM);

    cudaMemsetAsync(pagg, 0, (size_t)N * NF * sizeof(float));
    prep_weights_kernel<<<64, 256>>>(w1, w2, l1w, l2w, lw);
    // h = x @ lin1_w^T
    row_mma_kernel<<<148, NTHREAD, ROW_SMEM>>>(x, linblob + 0, nullptr, (float*)ph, N, 0);
    // fused edge: filter MLP (fp16 mma) + CFConv + v4 scatter, persistent
    edge_mma_kernel<<<148, NTHREAD_E, EDGE_SMEM>>>((const float*)ph, ei, ew, attr,
                                                   b1, b2, (float*)pagg, E);
    // out = ssp(agg @ lin2_w^T + l2b) @ lin_w^T + lb   (fused, no u round-trip)
    fused_out_kernel<<<148, NTHREAD_F, FUSE_SMEM>>>((const float*)pagg,
                                                    linblob + 2048, linblob + 4096,
                                                    l2b, lb, out, N);
}

// round 17
// speedup vs baseline: 5.0789x; 1.1735x over previous
#include <cuda_runtime.h>
#include <cuda_bf16.h>
#include <cuda_fp16.h>
#include <math.h>
#include <cstdint>

#define HIDDEN 128
#define NF 128
#define NG 50
#define MAXN 40000
#define NWARP 14
#define NTHREAD (NWARP * 32)
#define NWARP_E 16
#define NTHREAD_E (NWARP_E * 32)
#define NWARP_F 11
#define NTHREAD_F (NWARP_F * 32)

// ---------- helpers ----------
__device__ __forceinline__ void red_add_v4(float* p, float a, float b, float c, float d) {
    asm volatile("red.global.add.v4.f32 [%0], {%1,%2,%3,%4};"
                 :: "l"(p), "f"(a), "f"(b), "f"(c), "f"(d) : "memory");
}
__device__ __forceinline__ float sspf(float x) {
    return fmaxf(x, 0.f) + __logf(0.5f * (1.0f + __expf(-fabsf(x))));
}
__device__ __forceinline__ void h16_split(float v, float& hi, float& lo) {
    __half h = __float2half(v);
    hi = __half2float(h);
    lo = v - hi;
}
__device__ __forceinline__ uint32_t pack_h2(float v0, float v1) {
    __half2 p = __floats2half2_rn(v0, v1);   // v0 -> low half
    return *(uint32_t*)&p;
}
// fp16 mma
__device__ __forceinline__ void mma_f16(float* c, uint32_t a0, uint32_t a1,
                                        uint32_t a2, uint32_t a3,
                                        uint32_t b0, uint32_t b1) {
    asm volatile(
        "mma.sync.aligned.m16n8k16.row.col.f32.f16.f16.f32 "
        "{%0,%1,%2,%3}, {%4,%5,%6,%7}, {%8,%9}, {%0,%1,%2,%3};"
        : "+f"(c[0]), "+f"(c[1]), "+f"(c[2]), "+f"(c[3])
        : "r"(a0), "r"(a1), "r"(a2), "r"(a3), "r"(b0), "r"(b1));
}

// ---------- scratch ----------
__device__ float g_h[(size_t)MAXN * NF];
__device__ float g_agg[(size_t)MAXN * NF];
// edge fp16 frag blob: W1[4096] W2[8192] words = 48KB
__device__ uint4 g_wblob[6144];
// lin fp16 frag blobs: 3 x 8192 words = 96KB total
__device__ uint4 g_linblob[3 * 2048];

// ================= prep: build mma B-fragment tables (all fp16) =================
// B frag (col-major operand for D = A @ W^T): n = nt*8 + lane/4,
// k = kc*16 + (lane%4)*2 + reg*8, packed pair (k, k+1)
__global__ void prep_weights_kernel(const float* __restrict__ w1,
                                    const float* __restrict__ w2,
                                    const float* __restrict__ l1w,
                                    const float* __restrict__ l2w,
                                    const float* __restrict__ lw) {
    uint32_t* blob = (uint32_t*)g_wblob;
    uint32_t* lblob = (uint32_t*)g_linblob;
    int tid = blockIdx.x * blockDim.x + threadIdx.x;
    int stride = gridDim.x * blockDim.x;
    // W1 fp16: 16 nt x 4 kc x 2 reg x 32 lanes = 4096 words
    for (int i = tid; i < 4096; i += stride) {
        int lane = i & 31, reg = (i >> 5) & 1, kc = (i >> 6) & 3, nt = i >> 8;
        int n = nt * 8 + (lane >> 2);
        int k0 = kc * 16 + (lane & 3) * 2 + reg * 8;
        float v0 = (k0 < NG)     ? w1[n * NG + k0]     : 0.f;
        float v1 = (k0 + 1 < NG) ? w1[n * NG + k0 + 1] : 0.f;
        blob[i] = pack_h2(v0, v1);
    }
    // W2 + 3 lin mats (128x128) fp16: 16 nt x 8 kc x 2 reg x 32 lanes = 8192 words each
    for (int i = tid; i < 8192; i += stride) {
        int lane = i & 31, reg = (i >> 5) & 1, kc = (i >> 6) & 7, nt = i >> 9;
        int n = nt * 8 + (lane >> 2);
        int k0 = kc * 16 + (lane & 3) * 2 + reg * 8;
        blob[4096 + i] = pack_h2(w2[n * 128 + k0], w2[n * 128 + k0 + 1]);
        lblob[i]         = pack_h2(l1w[n * 128 + k0], l1w[n * 128 + k0 + 1]);
        lblob[8192 + i]  = pack_h2(l2w[n * 128 + k0], l2w[n * 128 + k0 + 1]);
        lblob[16384 + i] = pack_h2(lw[n * 128 + k0],  lw[n * 128 + k0 + 1]);
    }
}

// ================= persistent fused edge kernel =================
// stage1: A 1-term fp16 (attr); stage2: A 1-term fp16 (T); B 1-term fp16 both
// smem words: W1[4096] W2[8192] | B1[128] | B2[128] | scratch 16 x 1088
#define ESM_B1   12288
#define ESM_B2   12416
#define ESM_SCR  12544
#define EDGE_SMEM ((ESM_SCR + NWARP_E * 1088) * 4)   /* 119808 B */

__global__ __launch_bounds__(NTHREAD_E, 1)
void edge_mma_kernel(const float* __restrict__ h, const int* __restrict__ ei,
                     const float* __restrict__ ew, const float* __restrict__ attr,
                     const float* __restrict__ b1, const float* __restrict__ b2,
                     float* __restrict__ agg, int E) {
    extern __shared__ uint32_t sm[];
    float* smf = (float*)sm;
    int tid = threadIdx.x;
    int warp = tid >> 5, lane = tid & 31;
    int qr = lane >> 2, qc = lane & 3;

    // one-time: weights + biases to smem
    {
        uint4* dst = (uint4*)sm;
        for (int i = tid; i < 3072; i += NTHREAD_E) dst[i] = g_wblob[i];
        if (tid < 128) { smf[ESM_B1 + tid] = b1[tid]; smf[ESM_B2 + tid] = b2[tid]; }
    }
    __syncthreads();

    uint32_t* hiB = sm + ESM_SCR + warp * 1088;   // 16 rows x stride 68

    int ngroups = (E + 15) >> 4;
    for (int g = blockIdx.x * NWARP_E + warp; g < ngroups; g += gridDim.x * NWARP_E) {
        int e0 = g * 16;

        // ---- per-lane edge meta (lanes 0..15 own one edge each) ----
        int srcL = 0, dstL = 0; float cvL = 0.f;
        if (lane < 16) {
            int e = e0 + lane;
            bool valid = e < E;
            int ie = valid ? e : 0;
            srcL = ei[ie]; dstL = ei[E + ie];
            float w = ew[ie];
            cvL = valid ? 0.5f * (cospif(w * 0.1f) + 1.0f) : 0.f;
        }

        // ---- stage attr (16 rows x 25 pairs) as fp16 (1-term), stride 68 ----
        #pragma unroll 4
        for (int r = 0; r < 16; r++) {
            int e = e0 + r;
            float2 v = make_float2(0.f, 0.f);
            if (lane < 25 && e < E) v = *(const float2*)(attr + (size_t)e * NG + 2 * lane);
            hiB[r * 68 + lane] = pack_h2(v.x, v.y);
        }
        __syncwarp();

        // ---- stage 1: C = attr @ W1^T (K=64, 1-term x 1-term) ----
        float c[16][4];
        #pragma unroll
        for (int nt = 0; nt < 16; nt++)
            { c[nt][0] = 0.f; c[nt][1] = 0.f; c[nt][2] = 0.f; c[nt][3] = 0.f; }
        #pragma unroll
        for (int kc = 0; kc < 4; kc++) {
            int w0 = kc * 8 + qc;
            int rA = qr * 68, rB = (qr + 8) * 68;
            uint32_t ah0 = hiB[rA + w0],     ah1 = hiB[rB + w0];
            uint32_t ah2 = hiB[rA + w0 + 4], ah3 = hiB[rB + w0 + 4];
            #pragma unroll
            for (int nt = 0; nt < 16; nt++) {
                int fb = nt * 256 + kc * 64;
                uint32_t bh0 = sm[fb + lane], bh1 = sm[fb + 32 + lane];
                mma_f16(c[nt], ah0, ah1, ah2, ah3, bh0, bh1);
            }
        }
        __syncwarp();

        // ---- epilogue 1: T = ssp(C + b1) -> fp16 scratch (1-term, direct pack) ----
        #pragma unroll
        for (int nt = 0; nt < 16; nt++) {
            int col0 = nt * 8 + qc * 2;
            float2 bv = *(float2*)&smf[ESM_B1 + col0];
            float t0 = sspf(c[nt][0] + bv.x), t1 = sspf(c[nt][1] + bv.y);
            float t2 = sspf(c[nt][2] + bv.x), t3 = sspf(c[nt][3] + bv.y);
            int wi = nt * 4 + qc;
            int rA = qr * 68, rB = (qr + 8) * 68;
            hiB[rA + wi] = pack_h2(t0, t1);
            hiB[rB + wi] = pack_h2(t2, t3);
        }
        __syncwarp();

        // ---- stage 2: D = T @ W2^T (K=128, 1-term x 1-term) ----
        float d[16][4];
        #pragma unroll
        for (int nt = 0; nt < 16; nt++)
            { d[nt][0] = 0.f; d[nt][1] = 0.f; d[nt][2] = 0.f; d[nt][3] = 0.f; }
        #pragma unroll
        for (int kc = 0; kc < 8; kc++) {
            int w0 = kc * 8 + qc;
            int rA = qr * 68, rB = (qr + 8) * 68;
            uint32_t ah0 = hiB[rA + w0],     ah1 = hiB[rB + w0];
            uint32_t ah2 = hiB[rA + w0 + 4], ah3 = hiB[rB + w0 + 4];
            #pragma unroll
            for (int nt = 0; nt < 16; nt++) {
                int fb = 4096 + nt * 512 + kc * 64;
                uint32_t bh0 = sm[fb + lane], bh1 = sm[fb + 32 + lane];
                mma_f16(d[nt], ah0, ah1, ah2, ah3, bh0, bh1);
            }
        }

        // ---- epilogue 2 (transposed v4): Wf=(D+b2)*cv; msg=h[src]*Wf; agg[dst]+=msg ----
        {
            unsigned full = 0xffffffffu;
            int odd = lane & 1;
            int idx = qr + odd * 8;                 // edge row this lane owns post-transpose
            float cvM = __shfl_sync(full, cvL, idx);
            int sM = __shfl_sync(full, srcL, idx);
            int dM = __shfl_sync(full, dstL, idx);
            const float* hrow = h + (size_t)sM * NF;
            float* arow = agg + (size_t)dM * NF;
            int sub4 = (qc >> 1) * 4;
            #pragma unroll
            for (int nt = 0; nt < 16; nt++) {
                float sa = odd ? d[nt][0] : d[nt][2];
                float sb = odd ? d[nt][1] : d[nt][3];
                float ra = __shfl_xor_sync(full, sa, 1);
                float rb = __shfl_xor_sync(full, sb, 1);
                float v0 = odd ? ra : d[nt][0];
                float v1 = odd ? rb : d[nt][1];
                float v2 = odd ? d[nt][2] : ra;
                float v3 = odd ? d[nt][3] : rb;
                int basecol = nt * 8 + sub4;
                float4 bv = *(const float4*)&smf[ESM_B2 + basecol];
                float4 hv = *(const float4*)(hrow + basecol);
                red_add_v4(arow + basecol,
                           (v0 + bv.x) * cvM * hv.x, (v1 + bv.y) * cvM * hv.y,
                           (v2 + bv.z) * cvM * hv.z, (v3 + bv.w) * cvM * hv.w);
            }
        }
        __syncwarp();
    }
}

// ================= persistent mma row GEMM (fp16 2-term A, 1-term B) =================
// smem words: W[8192] | BIAS[128] | scratch 14 x 2176
#define RSM_BIAS 8192
#define RSM_SCR  8320
#define ROW_SMEM ((RSM_SCR + NWARP * 2176) * 4)    /* 155136 B */

__global__ __launch_bounds__(NTHREAD, 1)
void row_mma_kernel(const float* __restrict__ X, const uint4* __restrict__ wblob,
                    const float* __restrict__ B, float* __restrict__ Y,
                    int N, int doSsp) {
    extern __shared__ uint32_t sm[];
    float* smf = (float*)sm;
    int tid = threadIdx.x;
    int warp = tid >> 5, lane = tid & 31;
    int qr = lane >> 2, qc = lane & 3;

    {
        uint4* dst = (uint4*)sm;
        for (int i = tid; i < 2048; i += NTHREAD) dst[i] = wblob[i];
        if (tid < 128) smf[RSM_BIAS + tid] = B ? B[tid] : 0.f;
    }
    __syncthreads();

    uint32_t* hiB = sm + RSM_SCR + warp * 2176;
    uint32_t* loB = hiB + 1088;

    int ngroups = (N + 15) >> 4;
    for (int g = blockIdx.x * NWARP + warp; g < ngroups; g += gridDim.x * NWARP) {
        int n0 = g * 16;
        // ---- stage X rows (16 x 64 pairs) fp16 hi/lo, stride 68 ----
        #pragma unroll 4
        for (int r = 0; r < 16; r++) {
            int n = n0 + r;
            float2 vA = make_float2(0.f, 0.f), vB = vA;
            if (n < N) {
                const float* xp = X + (size_t)n * 128;
                vA = *(const float2*)(xp + 2 * lane);
                vB = *(const float2*)(xp + 64 + 2 * lane);
            }
            float h0, l0, h1, l1;
            h16_split(vA.x, h0, l0); h16_split(vA.y, h1, l1);
            hiB[r * 68 + lane] = pack_h2(h0, h1);
            loB[r * 68 + lane] = pack_h2(l0, l1);
            h16_split(vB.x, h0, l0); h16_split(vB.y, h1, l1);
            hiB[r * 68 + 32 + lane] = pack_h2(h0, h1);
            loB[r * 68 + 32 + lane] = pack_h2(l0, l1);
        }
        __syncwarp();

        float c[16][4];
        #pragma unroll
        for (int nt = 0; nt < 16; nt++)
            { c[nt][0] = 0.f; c[nt][1] = 0.f; c[nt][2] = 0.f; c[nt][3] = 0.f; }
        #pragma unroll
        for (int kc = 0; kc < 8; kc++) {
            int w0 = kc * 8 + qc;
            int rA = qr * 68, rB = (qr + 8) * 68;
            uint32_t ah0 = hiB[rA + w0],     ah1 = hiB[rB + w0];
            uint32_t ah2 = hiB[rA + w0 + 4], ah3 = hiB[rB + w0 + 4];
            uint32_t al0 = loB[rA + w0],     al1 = loB[rB + w0];
            uint32_t al2 = loB[rA + w0 + 4], al3 = loB[rB + w0 + 4];
            #pragma unroll
            for (int nt = 0; nt < 16; nt++) {
                int fb = nt * 512 + kc * 64;
                uint32_t bh0 = sm[fb + lane], bh1 = sm[fb + 32 + lane];
                mma_f16(c[nt], ah0, ah1, ah2, ah3, bh0, bh1);
                mma_f16(c[nt], al0, al1, al2, al3, bh0, bh1);
            }
        }

        // ---- epilogue ----
        int nA = n0 + qr, nB = n0 + qr + 8;
        #pragma unroll
        for (int nt = 0; nt < 16; nt++) {
            int col0 = nt * 8 + qc * 2;
            float2 bv = *(float2*)&smf[RSM_BIAS + col0];
            float o0 = c[nt][0] + bv.x, o1 = c[nt][1] + bv.y;
            float o2 = c[nt][2] + bv.x, o3 = c[nt][3] + bv.y;
            if (doSsp) { o0 = sspf(o0); o1 = sspf(o1); o2 = sspf(o2); o3 = sspf(o3); }
            if (nA < N) *(float2*)(Y + (size_t)nA * 128 + col0) = make_float2(o0, o1);
            if (nB < N) *(float2*)(Y + (size_t)nB * 128 + col0) = make_float2(o2, o3);
        }
        __syncwarp();
    }
}

// ================= fused output kernel (fp16): out = ssp(agg@l2w^T + l2b) @ lw^T + lb =================
// smem words: W2[8192] | W3[8192] | B2[128] | B3[128] | scratch 11 x 2176
#define FSM_W3   8192
#define FSM_B2   16384
#define FSM_B3   16512
#define FSM_SCR  16640
#define FUSE_SMEM ((FSM_SCR + NWARP_F * 2176) * 4)   /* 162304 B */

__global__ __launch_bounds__(NTHREAD_F, 1)
void fused_out_kernel(const float* __restrict__ X, const uint4* __restrict__ w2blob,
                      const uint4* __restrict__ w3blob,
                      const float* __restrict__ B2, const float* __restrict__ B3,
                      float* __restrict__ Y, int N) {
    extern __shared__ uint32_t sm[];
    float* smf = (float*)sm;
    int tid = threadIdx.x;
    int warp = tid >> 5, lane = tid & 31;
    int qr = lane >> 2, qc = lane & 3;

    {
        uint4* dst = (uint4*)sm;
        for (int i = tid; i < 2048; i += NTHREAD_F) dst[i] = w2blob[i];
        for (int i = tid; i < 2048; i += NTHREAD_F) dst[2048 + i] = w3blob[i];
        if (tid < 128) { smf[FSM_B2 + tid] = B2[tid]; smf[FSM_B3 + tid] = B3[tid]; }
    }
    __syncthreads();

    uint32_t* hiB = sm + FSM_SCR + warp * 2176;
    uint32_t* loB = hiB + 1088;

    int ngroups = (N + 15) >> 4;
    for (int g = blockIdx.x * NWARP_F + warp; g < ngroups; g += gridDim.x * NWARP_F) {
        int n0 = g * 16;
        // ---- stage X rows (16 x 64 pairs) fp16 hi/lo, stride 68 ----
        #pragma unroll 4
        for (int r = 0; r < 16; r++) {
            int n = n0 + r;
            float2 vA = make_float2(0.f, 0.f), vB = vA;
            if (n < N) {
                const float* xp = X + (size_t)n * 128;
                vA = *(const float2*)(xp + 2 * lane);
                vB = *(const float2*)(xp + 64 + 2 * lane);
            }
            float h0, l0, h1, l1;
            h16_split(vA.x, h0, l0); h16_split(vA.y, h1, l1);
            hiB[r * 68 + lane] = pack_h2(h0, h1);
            loB[r * 68 + lane] = pack_h2(l0, l1);
            h16_split(vB.x, h0, l0); h16_split(vB.y, h1, l1);
            hiB[r * 68 + 32 + lane] = pack_h2(h0, h1);
            loB[r * 68 + 32 + lane] = pack_h2(l0, l1);
        }
        __syncwarp();

        float c[16][4];
        // ---- stage 1: C = X @ l2w^T (fp16 2-term A, 1-term B) ----
        #pragma unroll
        for (int nt = 0; nt < 16; nt++)
            { c[nt][0] = 0.f; c[nt][1] = 0.f; c[nt][2] = 0.f; c[nt][3] = 0.f; }
        #pragma unroll
        for (int kc = 0; kc < 8; kc++) {
            int w0 = kc * 8 + qc;
            int rA = qr * 68, rB = (qr + 8) * 68;
            uint32_t ah0 = hiB[rA + w0],     ah1 = hiB[rB + w0];
            uint32_t ah2 = hiB[rA + w0 + 4], ah3 = hiB[rB + w0 + 4];
            uint32_t al0 = loB[rA + w0],     al1 = loB[rB + w0];
            uint32_t al2 = loB[rA + w0 + 4], al3 = loB[rB + w0 + 4];
            #pragma unroll
            for (int nt = 0; nt < 16; nt++) {
                int fb = nt * 512 + kc * 64;
                uint32_t bh0 = sm[fb + lane], bh1 = sm[fb + 32 + lane];
                mma_f16(c[nt], ah0, ah1, ah2, ah3, bh0, bh1);
                mma_f16(c[nt], al0, al1, al2, al3, bh0, bh1);
            }
        }
        __syncwarp();

        // ---- epilogue 1: T = ssp(C + l2b) -> fp16 hi/lo scratch ----
        #pragma unroll
        for (int nt = 0; nt < 16; nt++) {
            int col0 = nt * 8 + qc * 2;
            float2 bv = *(float2*)&smf[FSM_B2 + col0];
            float t0 = sspf(c[nt][0] + bv.x), t1 = sspf(c[nt][1] + bv.y);
            float t2 = sspf(c[nt][2] + bv.x), t3 = sspf(c[nt][3] + bv.y);
            float h0, l0, h1, l1, h2, l2, h3, l3;
            h16_split(t0, h0, l0); h16_split(t1, h1, l1);
            h16_split(t2, h2, l2); h16_split(t3, h3, l3);
            int wi = nt * 4 + qc;
            int rA = qr * 68, rB = (qr + 8) * 68;
            hiB[rA + wi] = pack_h2(h0, h1);
            loB[rA + wi] = pack_h2(l0, l1);
            hiB[rB + wi] = pack_h2(h2, h3);
            loB[rB + wi] = pack_h2(l2, l3);
        }
        __syncwarp();

        // ---- stage 2: C = T @ lw^T (fp16 2-term A, 1-term B) ----
        #pragma unroll
        for (int nt = 0; nt < 16; nt++)
            { c[nt][0] = 0.f; c[nt][1] = 0.f; c[nt][2] = 0.f; c[nt][3] = 0.f; }
        #pragma unroll
        for (int kc = 0; kc < 8; kc++) {
            int w0 = kc * 8 + qc;
            int rA = qr * 68, rB = (qr + 8) * 68;
            uint32_t ah0 = hiB[rA + w0],     ah1 = hiB[rB + w0];
            uint32_t ah2 = hiB[rA + w0 + 4], ah3 = hiB[rB + w0 + 4];
            uint32_t al0 = loB[rA + w0],     al1 = loB[rB + w0];
            uint32_t al2 = loB[rA + w0 + 4], al3 = loB[rB + w0 + 4];
            #pragma unroll
            for (int nt = 0; nt < 16; nt++) {
                int fb = FSM_W3 + nt * 512 + kc * 64;
                uint32_t bh0 = sm[fb + lane], bh1 = sm[fb + 32 + lane];
                mma_f16(c[nt], ah0, ah1, ah2, ah3, bh0, bh1);
                mma_f16(c[nt], al0, al1, al2, al3, bh0, bh1);
            }
        }

        // ---- epilogue 2: out = C + lb ----
        int nA = n0 + qr, nB = n0 + qr + 8;
        #pragma unroll
        for (int nt = 0; nt < 16; nt++) {
            int col0 = nt * 8 + qc * 2;
            float2 bv = *(float2*)&smf[FSM_B3 + col0];
            if (nA < N) *(float2*)(Y + (size_t)nA * 128 + col0)
                = make_float2(c[nt][0] + bv.x, c[nt][1] + bv.y);
            if (nB < N) *(float2*)(Y + (size_t)nB * 128 + col0)
                = make_float2(c[nt][2] + bv.x, c[nt][3] + bv.y);
        }
        __syncwarp();
    }
}

// =================================================================
extern "C" void kernel_launch(void* const* d_in, const int* in_sizes, int n_in,
                              void* d_out, int out_size) {
    const float* x    = (const float*)d_in[0];
    const int*   ei   = (const int*)  d_in[1];
    const float* ew   = (const float*)d_in[2];
    const float* attr = (const float*)d_in[3];
    const float* w1   = (const float*)d_in[4];
    const float* b1   = (const float*)d_in[5];
    const float* w2   = (const float*)d_in[6];
    const float* b2   = (const float*)d_in[7];
    const float* l1w  = (const float*)d_in[8];
    const float* l2w  = (const float*)d_in[9];
    const float* l2b  = (const float*)d_in[10];
    const float* lw   = (const float*)d_in[11];
    const float* lb   = (const float*)d_in[12];
    float* out = (float*)d_out;

    int N = in_sizes[0] / HIDDEN;
    int E = in_sizes[2];

    void *ph = nullptr, *pagg = nullptr, *plb = nullptr;
    cudaGetSymbolAddress(&ph,   g_h);
    cudaGetSymbolAddress(&pagg, g_agg);
    cudaGetSymbolAddress(&plb,  g_linblob);
    const uint4* linblob = (const uint4*)plb;

    (void)cudaFuncSetAttribute(row_mma_kernel,   cudaFuncAttributeMaxDynamicSharedMemorySize, ROW_SMEM);
    (void)cudaFuncSetAttribute(edge_mma_kernel,  cudaFuncAttributeMaxDynamicSharedMemorySize, EDGE_SMEM);
    (void)cudaFuncSetAttribute(fused_out_kernel, cudaFuncAttributeMaxDynamicSharedMemorySize, FUSE_SMEM);

    cudaMemsetAsync(pagg, 0, (size_t)N * NF * sizeof(float));
    prep_weights_kernel<<<64, 256>>>(w1, w2, l1w, l2w, lw);
    // h = x @ lin1_w^T
    row_mma_kernel<<<148, NTHREAD, ROW_SMEM>>>(x, linblob + 0, nullptr, (float*)ph, N, 0);
    // fused edge: filter MLP (fp16 1-term mma) + CFConv + v4 scatter, persistent
    edge_mma_kernel<<<148, NTHREAD_E, EDGE_SMEM>>>((const float*)ph, ei, ew, attr,
                                                   b1, b2, (float*)pagg, E);
    // out = ssp(agg @ lin2_w^T + l2b) @ lin_w^T + lb   (fused, no u round-trip)
    fused_out_kernel<<<148, NTHREAD_F, FUSE_SMEM>>>((const float*)pagg,
                                                    linblob + 2048, linblob + 4096,
                                                    l2b, lb, out, N);
}